// round 1
// baseline (speedup 1.0000x reference)
#include <cuda_runtime.h>
#include <math.h>
#include <stdint.h>

// ---------------- problem constants (shape-specialized) ----------------
#define B_   4
#define NP   8192
#define NI   1024
#define DP   512
#define DI   768
#define HH   512
#define DO   512
#define NQ   (B_ * NP)        // 32768 query rows
#define NIMG (B_ * NI)        // 4096 image rows
#define XDIM (DP + DO)        // 1024 concat dim
#define KNN_K 3
#define EPS_ 1e-6f

// ---------------- device scratch (static; no allocations allowed) ------
__device__ float g_himg [(size_t)NIMG * HH];      //  8 MB
__device__ float g_ifeat[(size_t)NIMG * DO];      //  8 MB
__device__ float g_xcat [(size_t)NQ * XDIM];      // 128 MB
__device__ float g_hg   [(size_t)NQ * HH];        //  64 MB
__device__ float g_hd   [(size_t)NQ * HH];        //  64 MB
__device__ float g_gl   [(size_t)NQ * DO];        //  64 MB
__device__ float g_dl   [(size_t)NQ * DO];        //  64 MB
__device__ float g_maskF[NIMG];
__device__ int   g_mask_mode;

// ---------------- mask dtype probe -------------------------------------
// mode 0 = float32, 1 = int32, 2 = bytes (bool). Reads only first 64 bytes
// (safe under every interpretation: min buffer is 4096 bytes).
__global__ void probe_mask_kernel(const void* mask) {
    const unsigned int* w = (const unsigned int*)mask;
    bool floatHit = false, multiByte = false;
    for (int i = 0; i < 16; i++) {
        unsigned int v = w[i];
        if (v == 0x3F800000u) floatHit = true;
        else if (v & 0xFFFFFF00u) multiByte = true;
    }
    g_mask_mode = floatHit ? 0 : (multiByte ? 2 : 1);
}

__global__ void normalize_mask_kernel(const void* mask) {
    int i = blockIdx.x * blockDim.x + threadIdx.x;
    if (i >= NIMG) return;
    int mode = g_mask_mode;
    float v;
    if (mode == 0)      v = ((const float*)mask)[i];
    else if (mode == 1) v = (float)((const int*)mask)[i];
    else                v = (float)((const unsigned char*)mask)[i];
    g_maskF[i] = (v != 0.0f) ? 1.0f : 0.0f;
}

// ---------------- tiled SGEMM: C = A(MxKd) * W(KdxN) + bias [, relu] ----
#define BM 128
#define BN 128
#define BK 8
#define TM 8
#define TN 8

template <bool RELU>
__global__ __launch_bounds__(256, 2)
void sgemm_bias_kernel(const float* __restrict__ A,
                       const float* __restrict__ W,
                       const float* __restrict__ bias,
                       float* __restrict__ C,
                       int M, int N, int Kd)
{
    __shared__ float As[BK][BM];
    __shared__ float Bs[BK][BN];

    const int tid = threadIdx.x;
    const int bx = blockIdx.x;   // N tile
    const int by = blockIdx.y;   // M tile

    const int a_row = tid >> 1;           // 0..127
    const int a_col = (tid & 1) << 2;     // 0 or 4
    const int b_row = tid >> 5;           // 0..7
    const int b_col = (tid & 31) << 2;    // 0..124

    const float* Ablk = A + (size_t)(by * BM) * Kd;
    const float* Wcol = W + (size_t)bx * BN;

    const int ty = tid >> 4;   // 0..15
    const int tx = tid & 15;   // 0..15

    float acc[TM][TN];
#pragma unroll
    for (int i = 0; i < TM; i++)
#pragma unroll
        for (int j = 0; j < TN; j++) acc[i][j] = 0.0f;

    for (int k0 = 0; k0 < Kd; k0 += BK) {
        float4 av = *(const float4*)(Ablk + (size_t)a_row * Kd + k0 + a_col);
        As[a_col + 0][a_row] = av.x;
        As[a_col + 1][a_row] = av.y;
        As[a_col + 2][a_row] = av.z;
        As[a_col + 3][a_row] = av.w;
        float4 bv = *(const float4*)(Wcol + (size_t)(k0 + b_row) * N + b_col);
        *(float4*)&Bs[b_row][b_col] = bv;
        __syncthreads();

#pragma unroll
        for (int k = 0; k < BK; k++) {
            float ar[TM], br[TN];
#pragma unroll
            for (int i = 0; i < TM; i++) ar[i] = As[k][ty * TM + i];
#pragma unroll
            for (int j = 0; j < TN; j++) br[j] = Bs[k][tx * TN + j];
#pragma unroll
            for (int i = 0; i < TM; i++)
#pragma unroll
                for (int j = 0; j < TN; j++)
                    acc[i][j] += ar[i] * br[j];
        }
        __syncthreads();
    }

#pragma unroll
    for (int i = 0; i < TM; i++) {
        int r = by * BM + ty * TM + i;
#pragma unroll
        for (int j = 0; j < TN; j += 4) {
            int c = bx * BN + tx * TN + j;
            float4 v;
            v.x = acc[i][j + 0] + bias[c + 0];
            v.y = acc[i][j + 1] + bias[c + 1];
            v.z = acc[i][j + 2] + bias[c + 2];
            v.w = acc[i][j + 3] + bias[c + 3];
            if (RELU) {
                v.x = fmaxf(v.x, 0.0f); v.y = fmaxf(v.y, 0.0f);
                v.z = fmaxf(v.z, 0.0f); v.w = fmaxf(v.w, 0.0f);
            }
            *(float4*)(C + (size_t)r * N + c) = v;
        }
    }
}

// ---------------- KNN (top-3) + weighted gather + concat ----------------
// One warp per query point. Block = 256 threads = 8 queries, all same batch.
__global__ __launch_bounds__(256)
void knn_gather_kernel(const float* __restrict__ patch_center,  // (B,Np,3)
                       const float* __restrict__ coord,         // (B,Ni,3)
                       const float* __restrict__ point_token)   // (B,Np,512)
{
    __shared__ float sx[NI], sy[NI], sz[NI], sm[NI];
    const int b = blockIdx.y;

    for (int i = threadIdx.x; i < NI; i += blockDim.x) {
        const float* cc = coord + ((size_t)b * NI + i) * 3;
        sx[i] = cc[0];
        sy[i] = cc[1];
        sz[i] = cc[2];
        sm[i] = g_maskF[b * NI + i];
    }
    __syncthreads();

    const int warp = threadIdx.x >> 5;
    const int lane = threadIdx.x & 31;
    const int p = blockIdx.x * 8 + warp;

    const float* q = patch_center + ((size_t)b * NP + p) * 3;
    const float qx = q[0], qy = q[1], qz = q[2];
    const float qs = qx * qx + qy * qy + qz * qz;

    const float INF = __int_as_float(0x7f800000);
    float bd0 = INF, bd1 = INF, bd2 = INF;
    int   bi0 = -1,  bi1 = -1,  bi2 = -1;

#pragma unroll 4
    for (int it = 0; it < NI / 32; it++) {
        int c = it * 32 + lane;
        float x = sx[c], y = sy[c], z = sz[c];
        float ss = x * x + y * y + z * z;
        float dot = qx * x + qy * y + qz * z;
        float d = fmaxf(qs + ss - 2.0f * dot, 0.0f);
        if (sm[c] == 0.0f) d = INF;
        if (d < bd2) {
            if (d < bd1) {
                bd2 = bd1; bi2 = bi1;
                if (d < bd0) { bd1 = bd0; bi1 = bi0; bd0 = d; bi0 = c; }
                else         { bd1 = d;   bi1 = c; }
            } else { bd2 = d; bi2 = c; }
        }
    }

    // merge 32 local top-3 lists -> global top-3 via 3 rounds of warp argmin
    float selD[KNN_K];
    int   selI[KNN_K];
    int ptr = 0;
#pragma unroll
    for (int r = 0; r < KNN_K; r++) {
        float cand = (ptr == 0) ? bd0 : (ptr == 1) ? bd1 : (ptr == 2) ? bd2 : INF;
        int   ci   = (ptr == 0) ? bi0 : (ptr == 1) ? bi1 : (ptr == 2) ? bi2 : -1;
        float m = cand;
#pragma unroll
        for (int o = 16; o > 0; o >>= 1) m = fminf(m, __shfl_xor_sync(0xffffffffu, m, o));
        unsigned ball = __ballot_sync(0xffffffffu, cand == m);
        int owner = __ffs(ball) - 1;
        selD[r] = m;
        selI[r] = __shfl_sync(0xffffffffu, ci, owner);
        if (lane == owner) ptr++;
        ptr = min(ptr, 3);
    }

    // inverse-distance weights
    float w[KNN_K], wsum = 0.0f;
#pragma unroll
    for (int r = 0; r < KNN_K; r++) {
        int idx = selI[r];
        float dist = sqrtf(selD[r]);
        float valid = (idx >= 0) ? sm[idx] : 0.0f;
        w[r] = valid / fmaxf(dist, EPS_);   // valid/inf -> 0
        wsum += w[r];
    }
    float inv = 1.0f / fmaxf(wsum, EPS_);
#pragma unroll
    for (int r = 0; r < KNN_K; r++) {
        w[r] *= inv;
        if (selI[r] < 0) selI[r] = 0;
    }

    const size_t row = (size_t)b * NP + p;
    const float* f0 = g_ifeat + ((size_t)b * NI + selI[0]) * DO;
    const float* f1 = g_ifeat + ((size_t)b * NI + selI[1]) * DO;
    const float* f2 = g_ifeat + ((size_t)b * NI + selI[2]) * DO;
    const float* pt = point_token + row * DP;
    float* xr = g_xcat + row * XDIM;

#pragma unroll 4
    for (int c = lane; c < DO; c += 32) {
        xr[c]      = pt[c];                                        // point half
        xr[DP + c] = w[0] * f0[c] + w[1] * f1[c] + w[2] * f2[c];   // aligned half
    }
}

// ---------------- fused epilogue: out = p + sigmoid(g)*d ----------------
__global__ void fuse_kernel(const float* __restrict__ point_token,
                            float* __restrict__ out)
{
    size_t i = (size_t)blockIdx.x * blockDim.x + threadIdx.x;
    if (i >= (size_t)NQ * DO) return;
    float g = g_gl[i];
    float d = g_dl[i];
    float s = 1.0f / (1.0f + expf(-g));
    out[i] = point_token[i] + s * d;
}

// ---------------- launch --------------------------------------------------
extern "C" void kernel_launch(void* const* d_in, const int* in_sizes, int n_in,
                              void* d_out, int out_size)
{
    const float* point_token  = (const float*)d_in[0];   // (4,8192,512)
    const float* patch_center = (const float*)d_in[1];   // (4,8192,3)
    const float* image_token  = (const float*)d_in[2];   // (4,1024,768)
    const float* image_coord  = (const float*)d_in[3];   // (4,1024,3)
    const void*  mask_raw     =               d_in[4];   // (4,1024) dtype probed
    const float* img_w1  = (const float*)d_in[5];
    const float* img_b1  = (const float*)d_in[6];
    const float* img_w2  = (const float*)d_in[7];
    const float* img_b2  = (const float*)d_in[8];
    const float* gate_w1 = (const float*)d_in[9];
    const float* gate_b1 = (const float*)d_in[10];
    const float* gate_w2 = (const float*)d_in[11];
    const float* gate_b2 = (const float*)d_in[12];
    const float* delta_w1 = (const float*)d_in[13];
    const float* delta_b1 = (const float*)d_in[14];
    const float* delta_w2 = (const float*)d_in[15];
    const float* delta_b2 = (const float*)d_in[16];
    float* out = (float*)d_out;

    float *himg, *ifeat, *xcat, *hg, *hd, *gl, *dl;
    cudaGetSymbolAddress((void**)&himg,  g_himg);
    cudaGetSymbolAddress((void**)&ifeat, g_ifeat);
    cudaGetSymbolAddress((void**)&xcat,  g_xcat);
    cudaGetSymbolAddress((void**)&hg,    g_hg);
    cudaGetSymbolAddress((void**)&hd,    g_hd);
    cudaGetSymbolAddress((void**)&gl,    g_gl);
    cudaGetSymbolAddress((void**)&dl,    g_dl);

    // 1. mask probe + normalize
    probe_mask_kernel<<<1, 1>>>(mask_raw);
    normalize_mask_kernel<<<(NIMG + 255) / 256, 256>>>(mask_raw);

    // 2. image MLP: (4096,768)->relu(512)->(512)
    sgemm_bias_kernel<true ><<<dim3(HH / BN, NIMG / BM), 256>>>(image_token, img_w1, img_b1, himg,  NIMG, HH, DI);
    sgemm_bias_kernel<false><<<dim3(DO / BN, NIMG / BM), 256>>>(himg,        img_w2, img_b2, ifeat, NIMG, DO, HH);

    // 3. KNN + weighted gather + concat into xcat (32768,1024)
    knn_gather_kernel<<<dim3(NP / 8, B_), 256>>>(patch_center, image_coord, point_token);

    // 4. gate MLP
    sgemm_bias_kernel<true ><<<dim3(HH / BN, NQ / BM), 256>>>(xcat, gate_w1, gate_b1, hg, NQ, HH, XDIM);
    sgemm_bias_kernel<false><<<dim3(DO / BN, NQ / BM), 256>>>(hg,   gate_w2, gate_b2, gl, NQ, DO, HH);

    // 5. delta MLP
    sgemm_bias_kernel<true ><<<dim3(HH / BN, NQ / BM), 256>>>(xcat, delta_w1, delta_b1, hd, NQ, HH, XDIM);
    sgemm_bias_kernel<false><<<dim3(DO / BN, NQ / BM), 256>>>(hd,   delta_w2, delta_b2, dl, NQ, DO, HH);

    // 6. fused residual gate
    fuse_kernel<<<((size_t)NQ * DO + 255) / 256, 256>>>(point_token, out);
}

// round 3
// speedup vs baseline: 2.4294x; 2.4294x over previous
#include <cuda_runtime.h>
#include <cuda_bf16.h>
#include <math.h>
#include <stdint.h>

// ---------------- problem constants (shape-specialized) ----------------
#define B_   4
#define NP   8192
#define NI   1024
#define DP   512
#define DI   768
#define HH   512
#define DO   512
#define NQ   (B_ * NP)        // 32768 query rows
#define NIMG (B_ * NI)        // 4096 image rows
#define XDIM (DP + DO)        // 1024 concat dim
#define KNN_K 3
#define EPS_ 1e-6f

// ---------------- device scratch (static; no allocations allowed) ------
__device__ __nv_bfloat16 g_Xhi [(size_t)NQ * XDIM];
__device__ __nv_bfloat16 g_Xlo [(size_t)NQ * XDIM];
__device__ __nv_bfloat16 g_Ghhi[(size_t)NQ * HH];
__device__ __nv_bfloat16 g_Ghlo[(size_t)NQ * HH];
__device__ __nv_bfloat16 g_Dhhi[(size_t)NQ * HH];
__device__ __nv_bfloat16 g_Dhlo[(size_t)NQ * HH];
__device__ __nv_bfloat16 g_Ihi [(size_t)NIMG * DI];
__device__ __nv_bfloat16 g_Ilo [(size_t)NIMG * DI];
__device__ __nv_bfloat16 g_Hihi[(size_t)NIMG * HH];
__device__ __nv_bfloat16 g_Hilo[(size_t)NIMG * HH];
__device__ float g_ifeat[(size_t)NIMG * DO];
__device__ float g_gl   [(size_t)NQ * DO];
__device__ float g_dl   [(size_t)NQ * DO];
// transposed+split weights, layout (N, K) K-major
__device__ __nv_bfloat16 g_iw1h[(size_t)HH * DI],  g_iw1l[(size_t)HH * DI];
__device__ __nv_bfloat16 g_iw2h[(size_t)DO * HH],  g_iw2l[(size_t)DO * HH];
__device__ __nv_bfloat16 g_gw1h[(size_t)HH * XDIM], g_gw1l[(size_t)HH * XDIM];
__device__ __nv_bfloat16 g_gw2h[(size_t)DO * HH],  g_gw2l[(size_t)DO * HH];
__device__ __nv_bfloat16 g_dw1h[(size_t)HH * XDIM], g_dw1l[(size_t)HH * XDIM];
__device__ __nv_bfloat16 g_dw2h[(size_t)DO * HH],  g_dw2l[(size_t)DO * HH];
__device__ float g_maskF[NIMG];
__device__ int   g_mask_mode;

// ---------------- helpers ----------------------------------------------
__device__ __forceinline__ uint32_t smem_u32_of(const void* p) {
    uint32_t a;
    asm("{ .reg .u64 t; cvta.to.shared.u64 t, %1; cvt.u32.u64 %0, t; }" : "=r"(a) : "l"(p));
    return a;
}
__device__ __forceinline__ void split_f32(float v, __nv_bfloat16& h, __nv_bfloat16& l) {
    h = __float2bfloat16_rn(v);
    l = __float2bfloat16_rn(v - __bfloat162float(h));
}

#define CP_ASYNC16(dst, src) \
    asm volatile("cp.async.cg.shared.global [%0], [%1], 16;" :: "r"(dst), "l"(src))
#define CP_COMMIT() asm volatile("cp.async.commit_group;" ::: "memory")
#define CP_WAIT1()  asm volatile("cp.async.wait_group 1;" ::: "memory")
#define CP_WAIT0()  asm volatile("cp.async.wait_group 0;" ::: "memory")

#define LDSM_X4(r0, r1, r2, r3, addr) \
    asm volatile("ldmatrix.sync.aligned.m8n8.x4.shared.b16 {%0,%1,%2,%3}, [%4];" \
        : "=r"(r0), "=r"(r1), "=r"(r2), "=r"(r3) : "r"(addr))

#define MMA_BF16(d, a, b0v, b1v)                                               \
    asm volatile("mma.sync.aligned.m16n8k16.row.col.f32.bf16.bf16.f32 "        \
        "{%0,%1,%2,%3}, {%4,%5,%6,%7}, {%8,%9}, {%0,%1,%2,%3};"                \
        : "+f"((d)[0]), "+f"((d)[1]), "+f"((d)[2]), "+f"((d)[3])               \
        : "r"((a)[0]), "r"((a)[1]), "r"((a)[2]), "r"((a)[3]),                  \
          "r"(b0v), "r"(b1v))

// ---------------- mask dtype probe -------------------------------------
__global__ void probe_mask_kernel(const void* mask) {
    const unsigned int* w = (const unsigned int*)mask;
    bool floatHit = false, multiByte = false;
    for (int i = 0; i < 16; i++) {
        unsigned int v = w[i];
        if (v == 0x3F800000u) floatHit = true;
        else if (v & 0xFFFFFF00u) multiByte = true;
    }
    g_mask_mode = floatHit ? 0 : (multiByte ? 2 : 1);
}
__global__ void normalize_mask_kernel(const void* mask) {
    int i = blockIdx.x * blockDim.x + threadIdx.x;
    if (i >= NIMG) return;
    int mode = g_mask_mode;
    float v;
    if (mode == 0)      v = ((const float*)mask)[i];
    else if (mode == 1) v = (float)((const int*)mask)[i];
    else                v = (float)((const unsigned char*)mask)[i];
    g_maskF[i] = (v != 0.0f) ? 1.0f : 0.0f;
}

// ---------------- weight transpose + split: W(K,N) -> Th,Tl (N,K) -------
__global__ void tsplit_kernel(const float* __restrict__ W,
                              __nv_bfloat16* __restrict__ Th,
                              __nv_bfloat16* __restrict__ Tl,
                              int K, int N)
{
    __shared__ float t[32][33];
    int n0 = blockIdx.x * 32, k0 = blockIdx.y * 32;
    int tx = threadIdx.x, ty = threadIdx.y;
    t[ty][tx] = W[(size_t)(k0 + ty) * N + n0 + tx];
    __syncthreads();
    float v = t[tx][ty];                 // = W[k0+tx][n0+ty]
    __nv_bfloat16 h, l; split_f32(v, h, l);
    size_t o = (size_t)(n0 + ty) * K + k0 + tx;
    Th[o] = h; Tl[o] = l;
}

// ---------------- generic f32 -> (hi,lo) split -------------------------
__global__ void split_kernel(const float* __restrict__ src,
                             __nv_bfloat16* __restrict__ dh,
                             __nv_bfloat16* __restrict__ dl, size_t n)
{
    size_t i = (size_t)blockIdx.x * blockDim.x + threadIdx.x;
    if (i >= n) return;
    __nv_bfloat16 h, l; split_f32(src[i], h, l);
    dh[i] = h; dl[i] = l;
}

// ---------------- mma.sync split-bf16 GEMM ------------------------------
// C(M,N) = (Ahi+Alo)(M,Kd) @ (Whi+Wlo)^T(N,Kd)  [products: hh + h*lo + lo*h]
// CTA tile 128x128, K-chunk 32 bf16, double-buffered cp.async.
// Smem tile: 128 rows x 32 cols bf16 = 8192 B, row = 64 B = 4 x 16B chunks,
// chunk swizzle: c' = c ^ (row & 3).
#define TILE_B 8192
#define STAGE_B (4 * TILE_B)      // Ah, Al, Wh, Wl
#define GEMM_SMEM (2 * STAGE_B)   // 64 KB

__device__ __forceinline__ void fill_async(const __nv_bfloat16* __restrict__ src,
                                           int ld, int k0, uint32_t sdst, int tid)
{
#pragma unroll
    for (int it = 0; it < 2; it++) {
        int idx = tid + it * 256;          // 0..511
        int row = idx >> 2, c = idx & 3;
        const void* g = src + (size_t)row * ld + k0 + c * 8;
        uint32_t d = sdst + row * 64 + ((c ^ (row & 3)) << 4);
        CP_ASYNC16(d, g);
    }
}

template <bool RELU_SPLIT>
__global__ void __launch_bounds__(256, 2)
gemm_mma_kernel(const __nv_bfloat16* __restrict__ Ahi,
                const __nv_bfloat16* __restrict__ Alo,
                const __nv_bfloat16* __restrict__ Whi,   // (N, Kd) K-major
                const __nv_bfloat16* __restrict__ Wlo,
                const float* __restrict__ bias,
                float* __restrict__ Cf32,
                __nv_bfloat16* __restrict__ Chi,
                __nv_bfloat16* __restrict__ Clo,
                int Kd, int Ncols)
{
    extern __shared__ char smem[];
    const uint32_t sbase = smem_u32_of(smem);
    const int tid = threadIdx.x;
    const int wid = tid >> 5;
    const int lane = tid & 31;
    const int wm = wid & 1;       // 2 M-blocks of 64
    const int wn = wid >> 1;      // 4 N-blocks of 32

    const __nv_bfloat16* At_h = Ahi + (size_t)blockIdx.y * 128 * Kd;
    const __nv_bfloat16* At_l = Alo + (size_t)blockIdx.y * 128 * Kd;
    const __nv_bfloat16* Wt_h = Whi + (size_t)blockIdx.x * 128 * Kd;
    const __nv_bfloat16* Wt_l = Wlo + (size_t)blockIdx.x * 128 * Kd;

    float acc[4][4][4];
#pragma unroll
    for (int i = 0; i < 4; i++)
#pragma unroll
        for (int j = 0; j < 4; j++)
#pragma unroll
            for (int r = 0; r < 4; r++) acc[i][j][r] = 0.0f;

    const int nch = Kd >> 5;

    // prefetch stage 0
    fill_async(At_h, Kd, 0, sbase + 0 * TILE_B, tid);
    fill_async(At_l, Kd, 0, sbase + 1 * TILE_B, tid);
    fill_async(Wt_h, Kd, 0, sbase + 2 * TILE_B, tid);
    fill_async(Wt_l, Kd, 0, sbase + 3 * TILE_B, tid);
    CP_COMMIT();

    // precomputed per-lane smem offsets (within a tile)
    const int a_row_in = lane & 15;          // row within m16
    const int a_kb     = lane >> 4;          // 0/1 -> k8 block
    const int b_n_in   = ((lane >> 4) << 3) + (lane & 7);  // n within n16
    const int b_kb     = (lane >> 3) & 1;    // 0/1 -> k8 block

    for (int c = 0; c < nch; c++) {
        if (c + 1 < nch) {
            const int k1 = (c + 1) << 5;
            const uint32_t st = sbase + ((c + 1) & 1) * STAGE_B;
            fill_async(At_h, Kd, k1, st + 0 * TILE_B, tid);
            fill_async(At_l, Kd, k1, st + 1 * TILE_B, tid);
            fill_async(Wt_h, Kd, k1, st + 2 * TILE_B, tid);
            fill_async(Wt_l, Kd, k1, st + 3 * TILE_B, tid);
            CP_COMMIT();
            CP_WAIT1();
        } else {
            CP_WAIT0();
        }
        __syncthreads();

        const uint32_t stg = sbase + (c & 1) * STAGE_B;
        const uint32_t sA_h = stg;
        const uint32_t sA_l = stg + TILE_B;
        const uint32_t sW_h = stg + 2 * TILE_B;
        const uint32_t sW_l = stg + 3 * TILE_B;

#pragma unroll
        for (int p = 0; p < 3; p++) {
            const uint32_t aB = (p == 2) ? sA_l : sA_h;
            const uint32_t bB = (p == 1) ? sW_l : sW_h;
#pragma unroll
            for (int s = 0; s < 2; s++) {
                uint32_t af[4][4];
#pragma unroll
                for (int mt = 0; mt < 4; mt++) {
                    int row = wm * 64 + mt * 16 + a_row_in;
                    int cc = s * 2 + a_kb;
                    uint32_t ad = aB + row * 64 + ((cc ^ (row & 3)) << 4);
                    LDSM_X4(af[mt][0], af[mt][1], af[mt][2], af[mt][3], ad);
                }
                uint32_t bf[2][4];
#pragma unroll
                for (int np = 0; np < 2; np++) {
                    int n = wn * 32 + np * 16 + b_n_in;
                    int cc = s * 2 + b_kb;
                    uint32_t bd = bB + n * 64 + ((cc ^ (n & 3)) << 4);
                    LDSM_X4(bf[np][0], bf[np][1], bf[np][2], bf[np][3], bd);
                }
#pragma unroll
                for (int mt = 0; mt < 4; mt++)
#pragma unroll
                    for (int nt = 0; nt < 4; nt++) {
                        uint32_t b0 = bf[nt >> 1][(nt & 1) * 2];
                        uint32_t b1 = bf[nt >> 1][(nt & 1) * 2 + 1];
                        MMA_BF16(acc[mt][nt], af[mt], b0, b1);
                    }
            }
        }
        __syncthreads();
    }

    // epilogue: fragment (mt,nt): rows wm*64+mt*16 + lane/4 (+8), cols wn*32+nt*8+(lane%4)*2
    const int rbase = blockIdx.y * 128 + wm * 64 + (lane >> 2);
    const int cbase = blockIdx.x * 128 + wn * 32 + ((lane & 3) << 1);
#pragma unroll
    for (int mt = 0; mt < 4; mt++) {
#pragma unroll
        for (int half = 0; half < 2; half++) {
            const int row = rbase + mt * 16 + half * 8;
#pragma unroll
            for (int nt = 0; nt < 4; nt++) {
                const int col = cbase + nt * 8;
                float v0 = acc[mt][nt][half * 2 + 0] + bias[col];
                float v1 = acc[mt][nt][half * 2 + 1] + bias[col + 1];
                if (RELU_SPLIT) {
                    v0 = fmaxf(v0, 0.0f);
                    v1 = fmaxf(v1, 0.0f);
                    __nv_bfloat16 h0, l0, h1, l1;
                    split_f32(v0, h0, l0);
                    split_f32(v1, h1, l1);
                    uint32_t hp = ((uint32_t)__bfloat16_as_ushort(h1) << 16) | __bfloat16_as_ushort(h0);
                    uint32_t lp = ((uint32_t)__bfloat16_as_ushort(l1) << 16) | __bfloat16_as_ushort(l0);
                    *(uint32_t*)(Chi + (size_t)row * Ncols + col) = hp;
                    *(uint32_t*)(Clo + (size_t)row * Ncols + col) = lp;
                } else {
                    float2 v; v.x = v0; v.y = v1;
                    *(float2*)(Cf32 + (size_t)row * Ncols + col) = v;
                }
            }
        }
    }
}

// ---------------- KNN (top-3) + weighted gather + split concat ----------
__global__ __launch_bounds__(256)
void knn_gather_kernel(const float* __restrict__ patch_center,  // (B,Np,3)
                       const float* __restrict__ coord,         // (B,Ni,3)
                       const float* __restrict__ point_token)   // (B,Np,512)
{
    __shared__ float sx[NI], sy[NI], sz[NI], sm[NI];
    const int b = blockIdx.y;

    for (int i = threadIdx.x; i < NI; i += blockDim.x) {
        const float* cc = coord + ((size_t)b * NI + i) * 3;
        sx[i] = cc[0]; sy[i] = cc[1]; sz[i] = cc[2];
        sm[i] = g_maskF[b * NI + i];
    }
    __syncthreads();

    const int warp = threadIdx.x >> 5;
    const int lane = threadIdx.x & 31;
    const int p = blockIdx.x * 8 + warp;

    const float* q = patch_center + ((size_t)b * NP + p) * 3;
    const float qx = q[0], qy = q[1], qz = q[2];
    const float qs = qx * qx + qy * qy + qz * qz;

    const float INF = __int_as_float(0x7f800000);
    float bd0 = INF, bd1 = INF, bd2 = INF;
    int   bi0 = -1,  bi1 = -1,  bi2 = -1;

#pragma unroll 4
    for (int it = 0; it < NI / 32; it++) {
        int c = it * 32 + lane;
        float x = sx[c], y = sy[c], z = sz[c];
        float ss = x * x + y * y + z * z;
        float dot = qx * x + qy * y + qz * z;
        float d = fmaxf(qs + ss - 2.0f * dot, 0.0f);
        if (sm[c] == 0.0f) d = INF;
        if (d < bd2) {
            if (d < bd1) {
                bd2 = bd1; bi2 = bi1;
                if (d < bd0) { bd1 = bd0; bi1 = bi0; bd0 = d; bi0 = c; }
                else         { bd1 = d;   bi1 = c; }
            } else { bd2 = d; bi2 = c; }
        }
    }

    float selD[KNN_K]; int selI[KNN_K];
    int ptr = 0;
#pragma unroll
    for (int r = 0; r < KNN_K; r++) {
        float cand = (ptr == 0) ? bd0 : (ptr == 1) ? bd1 : (ptr == 2) ? bd2 : INF;
        int   ci   = (ptr == 0) ? bi0 : (ptr == 1) ? bi1 : (ptr == 2) ? bi2 : -1;
        float m = cand;
#pragma unroll
        for (int o = 16; o > 0; o >>= 1) m = fminf(m, __shfl_xor_sync(0xffffffffu, m, o));
        unsigned ball = __ballot_sync(0xffffffffu, cand == m);
        int owner = __ffs(ball) - 1;
        selD[r] = m;
        selI[r] = __shfl_sync(0xffffffffu, ci, owner);
        if (lane == owner) ptr++;
        ptr = min(ptr, 3);
    }

    float w[KNN_K], wsum = 0.0f;
#pragma unroll
    for (int r = 0; r < KNN_K; r++) {
        int idx = selI[r];
        float dist = sqrtf(selD[r]);
        float valid = (idx >= 0) ? sm[idx] : 0.0f;
        w[r] = valid / fmaxf(dist, EPS_);
        wsum += w[r];
    }
    float inv = 1.0f / fmaxf(wsum, EPS_);
#pragma unroll
    for (int r = 0; r < KNN_K; r++) {
        w[r] *= inv;
        if (selI[r] < 0) selI[r] = 0;
    }

    const size_t row = (size_t)b * NP + p;
    const float* f0 = g_ifeat + ((size_t)b * NI + selI[0]) * DO;
    const float* f1 = g_ifeat + ((size_t)b * NI + selI[1]) * DO;
    const float* f2 = g_ifeat + ((size_t)b * NI + selI[2]) * DO;
    const float* pt = point_token + row * DP;
    __nv_bfloat16* xh = g_Xhi + row * XDIM;
    __nv_bfloat16* xl = g_Xlo + row * XDIM;

#pragma unroll 4
    for (int c = lane; c < DO; c += 32) {
        __nv_bfloat16 h, l;
        split_f32(pt[c], h, l);
        xh[c] = h; xl[c] = l;
        float a = w[0] * f0[c] + w[1] * f1[c] + w[2] * f2[c];
        split_f32(a, h, l);
        xh[DP + c] = h; xl[DP + c] = l;
    }
}

// ---------------- fused epilogue: out = p + sigmoid(g)*d ----------------
__global__ void fuse_kernel(const float* __restrict__ point_token,
                            float* __restrict__ out)
{
    size_t i = (size_t)blockIdx.x * blockDim.x + threadIdx.x;
    if (i >= (size_t)NQ * DO) return;
    float g = g_gl[i];
    float d = g_dl[i];
    float s = 1.0f / (1.0f + expf(-g));
    out[i] = point_token[i] + s * d;
}

// ---------------- launch --------------------------------------------------
extern "C" void kernel_launch(void* const* d_in, const int* in_sizes, int n_in,
                              void* d_out, int out_size)
{
    const float* point_token  = (const float*)d_in[0];
    const float* patch_center = (const float*)d_in[1];
    const float* image_token  = (const float*)d_in[2];
    const float* image_coord  = (const float*)d_in[3];
    const void*  mask_raw     =               d_in[4];
    const float* img_w1  = (const float*)d_in[5];
    const float* img_b1  = (const float*)d_in[6];
    const float* img_w2  = (const float*)d_in[7];
    const float* img_b2  = (const float*)d_in[8];
    const float* gate_w1 = (const float*)d_in[9];
    const float* gate_b1 = (const float*)d_in[10];
    const float* gate_w2 = (const float*)d_in[11];
    const float* gate_b2 = (const float*)d_in[12];
    const float* delta_w1 = (const float*)d_in[13];
    const float* delta_b1 = (const float*)d_in[14];
    const float* delta_w2 = (const float*)d_in[15];
    const float* delta_b2 = (const float*)d_in[16];
    float* out = (float*)d_out;

    __nv_bfloat16 *Xhi, *Xlo, *Ghhi, *Ghlo, *Dhhi, *Dhlo, *Ihi, *Ilo, *Hihi, *Hilo;
    __nv_bfloat16 *iw1h, *iw1l, *iw2h, *iw2l, *gw1h, *gw1l, *gw2h, *gw2l, *dw1h, *dw1l, *dw2h, *dw2l;
    float *ifeat, *gl, *dl;
    cudaGetSymbolAddress((void**)&Xhi,  g_Xhi);  cudaGetSymbolAddress((void**)&Xlo,  g_Xlo);
    cudaGetSymbolAddress((void**)&Ghhi, g_Ghhi); cudaGetSymbolAddress((void**)&Ghlo, g_Ghlo);
    cudaGetSymbolAddress((void**)&Dhhi, g_Dhhi); cudaGetSymbolAddress((void**)&Dhlo, g_Dhlo);
    cudaGetSymbolAddress((void**)&Ihi,  g_Ihi);  cudaGetSymbolAddress((void**)&Ilo,  g_Ilo);
    cudaGetSymbolAddress((void**)&Hihi, g_Hihi); cudaGetSymbolAddress((void**)&Hilo, g_Hilo);
    cudaGetSymbolAddress((void**)&iw1h, g_iw1h); cudaGetSymbolAddress((void**)&iw1l, g_iw1l);
    cudaGetSymbolAddress((void**)&iw2h, g_iw2h); cudaGetSymbolAddress((void**)&iw2l, g_iw2l);
    cudaGetSymbolAddress((void**)&gw1h, g_gw1h); cudaGetSymbolAddress((void**)&gw1l, g_gw1l);
    cudaGetSymbolAddress((void**)&gw2h, g_gw2h); cudaGetSymbolAddress((void**)&gw2l, g_gw2l);
    cudaGetSymbolAddress((void**)&dw1h, g_dw1h); cudaGetSymbolAddress((void**)&dw1l, g_dw1l);
    cudaGetSymbolAddress((void**)&dw2h, g_dw2h); cudaGetSymbolAddress((void**)&dw2l, g_dw2l);
    cudaGetSymbolAddress((void**)&ifeat, g_ifeat);
    cudaGetSymbolAddress((void**)&gl, g_gl);
    cudaGetSymbolAddress((void**)&dl, g_dl);

    cudaFuncSetAttribute(gemm_mma_kernel<true>,  cudaFuncAttributeMaxDynamicSharedMemorySize, GEMM_SMEM);
    cudaFuncSetAttribute(gemm_mma_kernel<false>, cudaFuncAttributeMaxDynamicSharedMemorySize, GEMM_SMEM);

    // 1. mask
    probe_mask_kernel<<<1, 1>>>(mask_raw);
    normalize_mask_kernel<<<(NIMG + 255) / 256, 256>>>(mask_raw);

    // 2. weight transpose+split (W (K,N) -> (N,K) hi/lo)
    tsplit_kernel<<<dim3(HH / 32, DI / 32),   dim3(32, 32)>>>(img_w1,  iw1h, iw1l, DI,   HH);
    tsplit_kernel<<<dim3(DO / 32, HH / 32),   dim3(32, 32)>>>(img_w2,  iw2h, iw2l, HH,   DO);
    tsplit_kernel<<<dim3(HH / 32, XDIM / 32), dim3(32, 32)>>>(gate_w1, gw1h, gw1l, XDIM, HH);
    tsplit_kernel<<<dim3(DO / 32, HH / 32),   dim3(32, 32)>>>(gate_w2, gw2h, gw2l, HH,   DO);
    tsplit_kernel<<<dim3(HH / 32, XDIM / 32), dim3(32, 32)>>>(delta_w1, dw1h, dw1l, XDIM, HH);
    tsplit_kernel<<<dim3(DO / 32, HH / 32),   dim3(32, 32)>>>(delta_w2, dw2h, dw2l, HH,   DO);

    // 3. image token split + image MLP
    split_kernel<<<((size_t)NIMG * DI + 255) / 256, 256>>>(image_token, Ihi, Ilo, (size_t)NIMG * DI);
    gemm_mma_kernel<true ><<<dim3(HH / 128, NIMG / 128), 256, GEMM_SMEM>>>(
        Ihi, Ilo, iw1h, iw1l, img_b1, nullptr, Hihi, Hilo, DI, HH);
    gemm_mma_kernel<false><<<dim3(DO / 128, NIMG / 128), 256, GEMM_SMEM>>>(
        Hihi, Hilo, iw2h, iw2l, img_b2, ifeat, nullptr, nullptr, HH, DO);

    // 4. KNN + gather -> split concat X
    knn_gather_kernel<<<dim3(NP / 8, B_), 256>>>(patch_center, image_coord, point_token);

    // 5. gate MLP
    gemm_mma_kernel<true ><<<dim3(HH / 128, NQ / 128), 256, GEMM_SMEM>>>(
        Xhi, Xlo, gw1h, gw1l, gate_b1, nullptr, Ghhi, Ghlo, XDIM, HH);
    gemm_mma_kernel<false><<<dim3(DO / 128, NQ / 128), 256, GEMM_SMEM>>>(
        Ghhi, Ghlo, gw2h, gw2l, gate_b2, gl, nullptr, nullptr, HH, DO);

    // 6. delta MLP
    gemm_mma_kernel<true ><<<dim3(HH / 128, NQ / 128), 256, GEMM_SMEM>>>(
        Xhi, Xlo, dw1h, dw1l, delta_b1, nullptr, Dhhi, Dhlo, XDIM, HH);
    gemm_mma_kernel<false><<<dim3(DO / 128, NQ / 128), 256, GEMM_SMEM>>>(
        Dhhi, Dhlo, dw2h, dw2l, delta_b2, dl, nullptr, nullptr, HH, DO);

    // 7. fused residual gate
    fuse_kernel<<<((size_t)NQ * DO + 255) / 256, 256>>>(point_token, out);
}

// round 4
// speedup vs baseline: 3.3104x; 1.3626x over previous
#include <cuda_runtime.h>
#include <cuda_fp16.h>
#include <math.h>
#include <stdint.h>

// ---------------- problem constants (shape-specialized) ----------------
#define B_   4
#define NP   8192
#define NI   1024
#define DP   512
#define DI   768
#define HH   512
#define DO   512
#define NQ   (B_ * NP)        // 32768 query rows
#define NIMG (B_ * NI)        // 4096 image rows
#define XDIM (DP + DO)        // 1024 concat dim
#define KNN_K 3
#define EPS_ 1e-6f

// ---------------- device scratch (static; no allocations allowed) ------
__device__ __half g_Xhi [(size_t)NQ * XDIM];
__device__ __half g_Xlo [(size_t)NQ * XDIM];
__device__ __half g_Ghhi[(size_t)NQ * HH];
__device__ __half g_Ghlo[(size_t)NQ * HH];
__device__ __half g_Dhhi[(size_t)NQ * HH];
__device__ __half g_Dhlo[(size_t)NQ * HH];
__device__ __half g_Ihi [(size_t)NIMG * DI];
__device__ __half g_Ilo [(size_t)NIMG * DI];
__device__ __half g_Hihi[(size_t)NIMG * HH];
__device__ __half g_Hilo[(size_t)NIMG * HH];
__device__ float g_ifeat[(size_t)NIMG * DO];
__device__ float g_gl   [(size_t)NQ * DO];
// transposed weights (hi only), layout (N, K) K-major, fp16
__device__ __half g_iw1h[(size_t)HH * DI];
__device__ __half g_iw2h[(size_t)DO * HH];
__device__ __half g_gw1h[(size_t)HH * XDIM];
__device__ __half g_gw2h[(size_t)DO * HH];
__device__ __half g_dw1h[(size_t)HH * XDIM];
__device__ __half g_dw2h[(size_t)DO * HH];
__device__ float g_maskF[NIMG];
__device__ int   g_mask_mode;

// ---------------- helpers ----------------------------------------------
__device__ __forceinline__ uint32_t smem_u32_of(const void* p) {
    uint32_t a;
    asm("{ .reg .u64 t; cvta.to.shared.u64 t, %1; cvt.u32.u64 %0, t; }" : "=r"(a) : "l"(p));
    return a;
}
__device__ __forceinline__ void split_f16(float v, __half& h, __half& l) {
    h = __float2half_rn(v);
    l = __float2half_rn(v - __half2float(h));
}

#define CP_ASYNC16(dst, src) \
    asm volatile("cp.async.cg.shared.global [%0], [%1], 16;" :: "r"(dst), "l"(src))
#define CP_COMMIT() asm volatile("cp.async.commit_group;" ::: "memory")
#define CP_WAIT2()  asm volatile("cp.async.wait_group 2;" ::: "memory")

#define LDSM_X4(r0, r1, r2, r3, addr) \
    asm volatile("ldmatrix.sync.aligned.m8n8.x4.shared.b16 {%0,%1,%2,%3}, [%4];" \
        : "=r"(r0), "=r"(r1), "=r"(r2), "=r"(r3) : "r"(addr))

#define MMA_F16(d, a, b0v, b1v)                                                \
    asm volatile("mma.sync.aligned.m16n8k16.row.col.f32.f16.f16.f32 "          \
        "{%0,%1,%2,%3}, {%4,%5,%6,%7}, {%8,%9}, {%0,%1,%2,%3};"                \
        : "+f"((d)[0]), "+f"((d)[1]), "+f"((d)[2]), "+f"((d)[3])               \
        : "r"((a)[0]), "r"((a)[1]), "r"((a)[2]), "r"((a)[3]),                  \
          "r"(b0v), "r"(b1v))

// ---------------- mask dtype probe -------------------------------------
__global__ void probe_mask_kernel(const void* mask) {
    const unsigned int* w = (const unsigned int*)mask;
    bool floatHit = false, multiByte = false;
    for (int i = 0; i < 16; i++) {
        unsigned int v = w[i];
        if (v == 0x3F800000u) floatHit = true;
        else if (v & 0xFFFFFF00u) multiByte = true;
    }
    g_mask_mode = floatHit ? 0 : (multiByte ? 2 : 1);
}
__global__ void normalize_mask_kernel(const void* mask) {
    int i = blockIdx.x * blockDim.x + threadIdx.x;
    if (i >= NIMG) return;
    int mode = g_mask_mode;
    float v;
    if (mode == 0)      v = ((const float*)mask)[i];
    else if (mode == 1) v = (float)((const int*)mask)[i];
    else                v = (float)((const unsigned char*)mask)[i];
    g_maskF[i] = (v != 0.0f) ? 1.0f : 0.0f;
}

// ---------------- weight transpose (hi fp16): W(K,N) -> Wh (N,K) --------
__global__ void tsplit_kernel(const float* __restrict__ W,
                              __half* __restrict__ Th,
                              int K, int N)
{
    __shared__ float t[32][33];
    int n0 = blockIdx.x * 32, k0 = blockIdx.y * 32;
    int tx = threadIdx.x, ty = threadIdx.y;
    t[ty][tx] = W[(size_t)(k0 + ty) * N + n0 + tx];
    __syncthreads();
    Th[(size_t)(n0 + ty) * K + k0 + tx] = __float2half_rn(t[tx][ty]);
}

// ---------------- generic f32 -> (hi,lo) fp16 split ---------------------
__global__ void split_kernel(const float* __restrict__ src,
                             __half* __restrict__ dh,
                             __half* __restrict__ dl, size_t n)
{
    size_t i = (size_t)blockIdx.x * blockDim.x + threadIdx.x;
    if (i >= n) return;
    __half h, l; split_f16(src[i], h, l);
    dh[i] = h; dl[i] = l;
}

// ---------------- mma.sync 2-product fp16 GEMM --------------------------
// C(M,N) = (Ahi+Alo)(M,Kd) @ Wh^T(N,Kd)
// CTA tile 128x128, K-chunk 32 fp16, 3-stage cp.async pipeline.
// Smem tile: 128 rows x 32 cols fp16 = 8192 B, row = 64 B = 4 x 16B chunks,
// chunk swizzle: c' = c ^ (row & 3).
#define TILE_B 8192
#define STAGE_B (3 * TILE_B)      // Ah, Al, Wh
#define GEMM_SMEM (3 * STAGE_B)   // 72 KB, 3 stages

// MODE: 0 = relu + fp16 split out, 1 = f32 + bias out, 2 = fused final out
template <int MODE, bool DUAL>
__global__ void __launch_bounds__(256, 2)
gemm_mma_kernel(const __half* __restrict__ Ahi,
                const __half* __restrict__ Alo,
                const __half* __restrict__ W1,    // (N, Kd) K-major fp16
                const __half* __restrict__ W2,    // DUAL: second weight set
                const float* __restrict__ bias1,
                const float* __restrict__ bias2,
                float* __restrict__ Cf32,
                __half* __restrict__ Chi1, __half* __restrict__ Clo1,
                __half* __restrict__ Chi2, __half* __restrict__ Clo2,
                const float* __restrict__ glp,    // MODE 2
                const float* __restrict__ pointp, // MODE 2
                int Kd, int Ncols, int nhalf)
{
    extern __shared__ char smem[];
    const uint32_t sbase = smem_u32_of(smem);
    const int tid = threadIdx.x;
    const int wid = tid >> 5;
    const int lane = tid & 31;
    const int wm = wid & 1;       // 2 M-blocks of 64
    const int wn = wid >> 1;      // 4 N-blocks of 32

    int bxn = blockIdx.x;
    const __half* Wsel = W1;
    const float* bias = bias1;
    __half* Chi = Chi1;
    __half* Clo = Clo1;
    if (DUAL && bxn >= nhalf) {
        bxn -= nhalf;
        Wsel = W2; bias = bias2; Chi = Chi2; Clo = Clo2;
    }

    const __half* At_h = Ahi + (size_t)blockIdx.y * 128 * Kd;
    const __half* At_l = Alo + (size_t)blockIdx.y * 128 * Kd;
    const __half* Wt   = Wsel + (size_t)bxn * 128 * Kd;

    float acc[4][4][4];
#pragma unroll
    for (int i = 0; i < 4; i++)
#pragma unroll
        for (int j = 0; j < 4; j++)
#pragma unroll
            for (int r = 0; r < 4; r++) acc[i][j][r] = 0.0f;

    const int nch = Kd >> 5;

    // fill one chunk's 3 tiles into a stage
    auto fill = [&](int ck) {
        const int k0 = ck << 5;
        const uint32_t st = sbase + (ck % 3) * STAGE_B;
#pragma unroll
        for (int it = 0; it < 2; it++) {
            int idx = tid + it * 256;          // 0..511
            int row = idx >> 2, cc = idx & 3;
            uint32_t soff = row * 64 + ((cc ^ (row & 3)) << 4);
            size_t goff = (size_t)row * Kd + k0 + cc * 8;
            CP_ASYNC16(st + 0 * TILE_B + soff, At_h + goff);
            CP_ASYNC16(st + 1 * TILE_B + soff, At_l + goff);
            CP_ASYNC16(st + 2 * TILE_B + soff, Wt + goff);
        }
    };

    fill(0); CP_COMMIT();
    fill(1); CP_COMMIT();

    const int a_row_in = lane & 15;
    const int a_kb     = lane >> 4;
    const int b_n_in   = ((lane >> 4) << 3) + (lane & 7);
    const int b_kb     = (lane >> 3) & 1;

    for (int c = 0; c < nch; c++) {
        if (c + 2 < nch) fill(c + 2);
        CP_COMMIT();
        CP_WAIT2();
        __syncthreads();

        const uint32_t stg = sbase + (c % 3) * STAGE_B;
        const uint32_t sA_h = stg;
        const uint32_t sA_l = stg + TILE_B;
        const uint32_t sW   = stg + 2 * TILE_B;

#pragma unroll
        for (int s = 0; s < 2; s++) {
            // B fragments (shared by both products)
            uint32_t bf[2][4];
#pragma unroll
            for (int np = 0; np < 2; np++) {
                int n = wn * 32 + np * 16 + b_n_in;
                int cc = s * 2 + b_kb;
                uint32_t bd = sW + n * 64 + ((cc ^ (n & 3)) << 4);
                LDSM_X4(bf[np][0], bf[np][1], bf[np][2], bf[np][3], bd);
            }
#pragma unroll
            for (int mt = 0; mt < 4; mt++) {
                int row = wm * 64 + mt * 16 + a_row_in;
                int cc = s * 2 + a_kb;
                uint32_t ah[4], al[4];
                uint32_t adh = sA_h + row * 64 + ((cc ^ (row & 3)) << 4);
                uint32_t adl = sA_l + row * 64 + ((cc ^ (row & 3)) << 4);
                LDSM_X4(ah[0], ah[1], ah[2], ah[3], adh);
                LDSM_X4(al[0], al[1], al[2], al[3], adl);
#pragma unroll
                for (int nt = 0; nt < 4; nt++) {
                    uint32_t b0 = bf[nt >> 1][(nt & 1) * 2];
                    uint32_t b1 = bf[nt >> 1][(nt & 1) * 2 + 1];
                    MMA_F16(acc[mt][nt], ah, b0, b1);
                }
#pragma unroll
                for (int nt = 0; nt < 4; nt++) {
                    uint32_t b0 = bf[nt >> 1][(nt & 1) * 2];
                    uint32_t b1 = bf[nt >> 1][(nt & 1) * 2 + 1];
                    MMA_F16(acc[mt][nt], al, b0, b1);
                }
            }
        }
        __syncthreads();
    }

    // epilogue
    const int rbase = blockIdx.y * 128 + wm * 64 + (lane >> 2);
    const int cbase = bxn * 128 + wn * 32 + ((lane & 3) << 1);
#pragma unroll
    for (int mt = 0; mt < 4; mt++) {
#pragma unroll
        for (int half = 0; half < 2; half++) {
            const int row = rbase + mt * 16 + half * 8;
#pragma unroll
            for (int nt = 0; nt < 4; nt++) {
                const int col = cbase + nt * 8;
                float v0 = acc[mt][nt][half * 2 + 0] + bias[col];
                float v1 = acc[mt][nt][half * 2 + 1] + bias[col + 1];
                if (MODE == 0) {
                    v0 = fmaxf(v0, 0.0f);
                    v1 = fmaxf(v1, 0.0f);
                    __half h0, l0, h1, l1;
                    split_f16(v0, h0, l0);
                    split_f16(v1, h1, l1);
                    uint32_t hp = ((uint32_t)__half_as_ushort(h1) << 16) | __half_as_ushort(h0);
                    uint32_t lp = ((uint32_t)__half_as_ushort(l1) << 16) | __half_as_ushort(l0);
                    *(uint32_t*)(Chi + (size_t)row * Ncols + col) = hp;
                    *(uint32_t*)(Clo + (size_t)row * Ncols + col) = lp;
                } else if (MODE == 1) {
                    float2 v; v.x = v0; v.y = v1;
                    *(float2*)(Cf32 + (size_t)row * Ncols + col) = v;
                } else {
                    // out = point + sigmoid(gl) * delta
                    size_t o = (size_t)row * Ncols + col;
                    float g0 = glp[o], g1 = glp[o + 1];
                    float s0 = 1.0f / (1.0f + expf(-g0));
                    float s1 = 1.0f / (1.0f + expf(-g1));
                    float2 v;
                    v.x = pointp[o]     + s0 * v0;
                    v.y = pointp[o + 1] + s1 * v1;
                    *(float2*)(Cf32 + o) = v;
                }
            }
        }
    }
}

// ---------------- KNN (top-3) + weighted gather + split concat ----------
__global__ __launch_bounds__(256)
void knn_gather_kernel(const float* __restrict__ patch_center,  // (B,Np,3)
                       const float* __restrict__ coord,         // (B,Ni,3)
                       const float* __restrict__ point_token)   // (B,Np,512)
{
    __shared__ float sx[NI], sy[NI], sz[NI], sm[NI];
    const int b = blockIdx.y;

    for (int i = threadIdx.x; i < NI; i += blockDim.x) {
        const float* cc = coord + ((size_t)b * NI + i) * 3;
        sx[i] = cc[0]; sy[i] = cc[1]; sz[i] = cc[2];
        sm[i] = g_maskF[b * NI + i];
    }
    __syncthreads();

    const int warp = threadIdx.x >> 5;
    const int lane = threadIdx.x & 31;
    const int p = blockIdx.x * 8 + warp;

    const float* q = patch_center + ((size_t)b * NP + p) * 3;
    const float qx = q[0], qy = q[1], qz = q[2];
    const float qs = qx * qx + qy * qy + qz * qz;

    const float INF = __int_as_float(0x7f800000);
    float bd0 = INF, bd1 = INF, bd2 = INF;
    int   bi0 = -1,  bi1 = -1,  bi2 = -1;

#pragma unroll 4
    for (int it = 0; it < NI / 32; it++) {
        int c = it * 32 + lane;
        float x = sx[c], y = sy[c], z = sz[c];
        float ss = x * x + y * y + z * z;
        float dot = qx * x + qy * y + qz * z;
        float d = fmaxf(qs + ss - 2.0f * dot, 0.0f);
        if (sm[c] == 0.0f) d = INF;
        if (d < bd2) {
            if (d < bd1) {
                bd2 = bd1; bi2 = bi1;
                if (d < bd0) { bd1 = bd0; bi1 = bi0; bd0 = d; bi0 = c; }
                else         { bd1 = d;   bi1 = c; }
            } else { bd2 = d; bi2 = c; }
        }
    }

    float selD[KNN_K]; int selI[KNN_K];
    int ptr = 0;
#pragma unroll
    for (int r = 0; r < KNN_K; r++) {
        float cand = (ptr == 0) ? bd0 : (ptr == 1) ? bd1 : (ptr == 2) ? bd2 : INF;
        int   ci   = (ptr == 0) ? bi0 : (ptr == 1) ? bi1 : (ptr == 2) ? bi2 : -1;
        float m = cand;
#pragma unroll
        for (int o = 16; o > 0; o >>= 1) m = fminf(m, __shfl_xor_sync(0xffffffffu, m, o));
        unsigned ball = __ballot_sync(0xffffffffu, cand == m);
        int owner = __ffs(ball) - 1;
        selD[r] = m;
        selI[r] = __shfl_sync(0xffffffffu, ci, owner);
        if (lane == owner) ptr++;
        ptr = min(ptr, 3);
    }

    float w[KNN_K], wsum = 0.0f;
#pragma unroll
    for (int r = 0; r < KNN_K; r++) {
        int idx = selI[r];
        float dist = sqrtf(selD[r]);
        float valid = (idx >= 0) ? sm[idx] : 0.0f;
        w[r] = valid / fmaxf(dist, EPS_);
        wsum += w[r];
    }
    float inv = 1.0f / fmaxf(wsum, EPS_);
#pragma unroll
    for (int r = 0; r < KNN_K; r++) {
        w[r] *= inv;
        if (selI[r] < 0) selI[r] = 0;
    }

    const size_t row = (size_t)b * NP + p;
    const float* f0 = g_ifeat + ((size_t)b * NI + selI[0]) * DO;
    const float* f1 = g_ifeat + ((size_t)b * NI + selI[1]) * DO;
    const float* f2 = g_ifeat + ((size_t)b * NI + selI[2]) * DO;
    const float* pt = point_token + row * DP;
    __half* xh = g_Xhi + row * XDIM;
    __half* xl = g_Xlo + row * XDIM;

#pragma unroll 4
    for (int c = lane; c < DO; c += 32) {
        __half h, l;
        split_f16(pt[c], h, l);
        xh[c] = h; xl[c] = l;
        float a = w[0] * f0[c] + w[1] * f1[c] + w[2] * f2[c];
        split_f16(a, h, l);
        xh[DP + c] = h; xl[DP + c] = l;
    }
}

// ---------------- launch --------------------------------------------------
extern "C" void kernel_launch(void* const* d_in, const int* in_sizes, int n_in,
                              void* d_out, int out_size)
{
    const float* point_token  = (const float*)d_in[0];
    const float* patch_center = (const float*)d_in[1];
    const float* image_token  = (const float*)d_in[2];
    const float* image_coord  = (const float*)d_in[3];
    const void*  mask_raw     =               d_in[4];
    const float* img_w1  = (const float*)d_in[5];
    const float* img_b1  = (const float*)d_in[6];
    const float* img_w2  = (const float*)d_in[7];
    const float* img_b2  = (const float*)d_in[8];
    const float* gate_w1 = (const float*)d_in[9];
    const float* gate_b1 = (const float*)d_in[10];
    const float* gate_w2 = (const float*)d_in[11];
    const float* gate_b2 = (const float*)d_in[12];
    const float* delta_w1 = (const float*)d_in[13];
    const float* delta_b1 = (const float*)d_in[14];
    const float* delta_w2 = (const float*)d_in[15];
    const float* delta_b2 = (const float*)d_in[16];
    float* out = (float*)d_out;

    __half *Xhi, *Xlo, *Ghhi, *Ghlo, *Dhhi, *Dhlo, *Ihi, *Ilo, *Hihi, *Hilo;
    __half *iw1h, *iw2h, *gw1h, *gw2h, *dw1h, *dw2h;
    float *ifeat, *gl;
    cudaGetSymbolAddress((void**)&Xhi,  g_Xhi);  cudaGetSymbolAddress((void**)&Xlo,  g_Xlo);
    cudaGetSymbolAddress((void**)&Ghhi, g_Ghhi); cudaGetSymbolAddress((void**)&Ghlo, g_Ghlo);
    cudaGetSymbolAddress((void**)&Dhhi, g_Dhhi); cudaGetSymbolAddress((void**)&Dhlo, g_Dhlo);
    cudaGetSymbolAddress((void**)&Ihi,  g_Ihi);  cudaGetSymbolAddress((void**)&Ilo,  g_Ilo);
    cudaGetSymbolAddress((void**)&Hihi, g_Hihi); cudaGetSymbolAddress((void**)&Hilo, g_Hilo);
    cudaGetSymbolAddress((void**)&iw1h, g_iw1h);
    cudaGetSymbolAddress((void**)&iw2h, g_iw2h);
    cudaGetSymbolAddress((void**)&gw1h, g_gw1h);
    cudaGetSymbolAddress((void**)&gw2h, g_gw2h);
    cudaGetSymbolAddress((void**)&dw1h, g_dw1h);
    cudaGetSymbolAddress((void**)&dw2h, g_dw2h);
    cudaGetSymbolAddress((void**)&ifeat, g_ifeat);
    cudaGetSymbolAddress((void**)&gl, g_gl);

    cudaFuncSetAttribute(gemm_mma_kernel<0, false>, cudaFuncAttributeMaxDynamicSharedMemorySize, GEMM_SMEM);
    cudaFuncSetAttribute(gemm_mma_kernel<0, true>,  cudaFuncAttributeMaxDynamicSharedMemorySize, GEMM_SMEM);
    cudaFuncSetAttribute(gemm_mma_kernel<1, false>, cudaFuncAttributeMaxDynamicSharedMemorySize, GEMM_SMEM);
    cudaFuncSetAttribute(gemm_mma_kernel<2, false>, cudaFuncAttributeMaxDynamicSharedMemorySize, GEMM_SMEM);

    // 1. mask
    probe_mask_kernel<<<1, 1>>>(mask_raw);
    normalize_mask_kernel<<<(NIMG + 255) / 256, 256>>>(mask_raw);

    // 2. weight transpose to fp16 (W (K,N) -> (N,K))
    tsplit_kernel<<<dim3(HH / 32, DI / 32),   dim3(32, 32)>>>(img_w1,  iw1h, DI,   HH);
    tsplit_kernel<<<dim3(DO / 32, HH / 32),   dim3(32, 32)>>>(img_w2,  iw2h, HH,   DO);
    tsplit_kernel<<<dim3(HH / 32, XDIM / 32), dim3(32, 32)>>>(gate_w1, gw1h, XDIM, HH);
    tsplit_kernel<<<dim3(DO / 32, HH / 32),   dim3(32, 32)>>>(gate_w2, gw2h, HH,   DO);
    tsplit_kernel<<<dim3(HH / 32, XDIM / 32), dim3(32, 32)>>>(delta_w1, dw1h, XDIM, HH);
    tsplit_kernel<<<dim3(DO / 32, HH / 32),   dim3(32, 32)>>>(delta_w2, dw2h, HH,   DO);

    // 3. image token split + image MLP
    split_kernel<<<((size_t)NIMG * DI + 255) / 256, 256>>>(image_token, Ihi, Ilo, (size_t)NIMG * DI);
    gemm_mma_kernel<0, false><<<dim3(HH / 128, NIMG / 128), 256, GEMM_SMEM>>>(
        Ihi, Ilo, iw1h, nullptr, img_b1, nullptr,
        nullptr, Hihi, Hilo, nullptr, nullptr, nullptr, nullptr, DI, HH, 0);
    gemm_mma_kernel<1, false><<<dim3(DO / 128, NIMG / 128), 256, GEMM_SMEM>>>(
        Hihi, Hilo, iw2h, nullptr, img_b2, nullptr,
        ifeat, nullptr, nullptr, nullptr, nullptr, nullptr, nullptr, HH, DO, 0);

    // 4. KNN + gather -> split concat X
    knn_gather_kernel<<<dim3(NP / 8, B_), 256>>>(patch_center, image_coord, point_token);

    // 5. fused gate+delta layer-1 (shared X)
    gemm_mma_kernel<0, true><<<dim3(2 * HH / 128, NQ / 128), 256, GEMM_SMEM>>>(
        Xhi, Xlo, gw1h, dw1h, gate_b1, delta_b1,
        nullptr, Ghhi, Ghlo, Dhhi, Dhlo, nullptr, nullptr, XDIM, HH, HH / 128);

    // 6. gate layer-2 -> gl (f32 logits)
    gemm_mma_kernel<1, false><<<dim3(DO / 128, NQ / 128), 256, GEMM_SMEM>>>(
        Ghhi, Ghlo, gw2h, nullptr, gate_b2, nullptr,
        gl, nullptr, nullptr, nullptr, nullptr, nullptr, nullptr, HH, DO, 0);

    // 7. delta layer-2 fused with final gate/residual -> out
    gemm_mma_kernel<2, false><<<dim3(DO / 128, NQ / 128), 256, GEMM_SMEM>>>(
        Dhhi, Dhlo, dw2h, nullptr, delta_b2, nullptr,
        out, nullptr, nullptr, nullptr, nullptr, gl, point_token, HH, DO, 0);
}

// round 5
// speedup vs baseline: 4.9542x; 1.4965x over previous
#include <cuda_runtime.h>
#include <cuda_fp16.h>
#include <math.h>
#include <stdint.h>

// ---------------- problem constants (shape-specialized) ----------------
#define B_   4
#define NP   8192
#define NI   1024
#define DP   512
#define DI   768
#define HH   512
#define DO   512
#define NQ   (B_ * NP)        // 32768 query rows
#define NIMG (B_ * NI)        // 4096 image rows
#define XDIM (DP + DO)        // 1024 concat dim
#define KNN_K 3
#define EPS_ 1e-6f

// ---------------- device scratch (static; no allocations allowed) ------
__device__ __half g_X  [(size_t)NQ * XDIM];     // 64 MB
__device__ __half g_Gh [(size_t)NQ * HH];       // 32 MB
__device__ __half g_Dh [(size_t)NQ * HH];       // 32 MB
__device__ __half g_I  [(size_t)NIMG * DI];     //  6 MB
__device__ __half g_Hi [(size_t)NIMG * HH];     //  4 MB
__device__ float g_ifeat[(size_t)NIMG * DO];    //  8 MB
__device__ float g_gl   [(size_t)NQ * DO];      // 64 MB
// transposed weights, layout (N, K) K-major, fp16
__device__ __half g_iw1[(size_t)HH * DI];
__device__ __half g_iw2[(size_t)DO * HH];
__device__ __half g_gw1[(size_t)HH * XDIM];
__device__ __half g_gw2[(size_t)DO * HH];
__device__ __half g_dw1[(size_t)HH * XDIM];
__device__ __half g_dw2[(size_t)DO * HH];
__device__ float g_maskF[NIMG];
__device__ int   g_mask_mode;

// ---------------- helpers ----------------------------------------------
__device__ __forceinline__ uint32_t smem_u32_of(const void* p) {
    uint32_t a;
    asm("{ .reg .u64 t; cvta.to.shared.u64 t, %1; cvt.u32.u64 %0, t; }" : "=r"(a) : "l"(p));
    return a;
}

#define CP_ASYNC16(dst, src) \
    asm volatile("cp.async.cg.shared.global [%0], [%1], 16;" :: "r"(dst), "l"(src))
#define CP_COMMIT() asm volatile("cp.async.commit_group;" ::: "memory")
#define CP_WAIT2()  asm volatile("cp.async.wait_group 2;" ::: "memory")

#define LDSM_X4(r0, r1, r2, r3, addr) \
    asm volatile("ldmatrix.sync.aligned.m8n8.x4.shared.b16 {%0,%1,%2,%3}, [%4];" \
        : "=r"(r0), "=r"(r1), "=r"(r2), "=r"(r3) : "r"(addr))

#define MMA_F16(d, a, b0v, b1v)                                                \
    asm volatile("mma.sync.aligned.m16n8k16.row.col.f32.f16.f16.f32 "          \
        "{%0,%1,%2,%3}, {%4,%5,%6,%7}, {%8,%9}, {%0,%1,%2,%3};"                \
        : "+f"((d)[0]), "+f"((d)[1]), "+f"((d)[2]), "+f"((d)[3])               \
        : "r"((a)[0]), "r"((a)[1]), "r"((a)[2]), "r"((a)[3]),                  \
          "r"(b0v), "r"(b1v))

// ---------------- mask dtype probe -------------------------------------
__global__ void probe_mask_kernel(const void* mask) {
    const unsigned int* w = (const unsigned int*)mask;
    bool floatHit = false, multiByte = false;
    for (int i = 0; i < 16; i++) {
        unsigned int v = w[i];
        if (v == 0x3F800000u) floatHit = true;
        else if (v & 0xFFFFFF00u) multiByte = true;
    }
    g_mask_mode = floatHit ? 0 : (multiByte ? 2 : 1);
}
__global__ void normalize_mask_kernel(const void* mask) {
    int i = blockIdx.x * blockDim.x + threadIdx.x;
    if (i >= NIMG) return;
    int mode = g_mask_mode;
    float v;
    if (mode == 0)      v = ((const float*)mask)[i];
    else if (mode == 1) v = (float)((const int*)mask)[i];
    else                v = (float)((const unsigned char*)mask)[i];
    g_maskF[i] = (v != 0.0f) ? 1.0f : 0.0f;
}

// ---------------- weight transpose fp16: W(K,N) -> Wh (N,K) -------------
__global__ void tsplit_kernel(const float* __restrict__ W,
                              __half* __restrict__ Th,
                              int K, int N)
{
    __shared__ float t[32][33];
    int n0 = blockIdx.x * 32, k0 = blockIdx.y * 32;
    int tx = threadIdx.x, ty = threadIdx.y;
    t[ty][tx] = W[(size_t)(k0 + ty) * N + n0 + tx];
    __syncthreads();
    Th[(size_t)(n0 + ty) * K + k0 + tx] = __float2half_rn(t[tx][ty]);
}

// ---------------- generic f32 -> fp16 convert ---------------------------
__global__ void cvt_kernel(const float* __restrict__ src,
                           __half* __restrict__ dst, size_t n)
{
    size_t i = (size_t)blockIdx.x * blockDim.x + threadIdx.x;
    if (i >= n) return;
    float2 v = ((const float2*)src)[i];
    __half2 h = __floats2half2_rn(v.x, v.y);
    ((__half2*)dst)[i] = h;
}

// ---------------- mma.sync fp16 GEMM ------------------------------------
// C(M,N) = A(M,Kd) @ W^T(N,Kd),  fp16 inputs, f32 accum.
// CTA tile 128x128, K-chunk 32 fp16, 3-stage cp.async pipeline.
// Smem tile: 128 rows x 32 cols fp16 = 8192 B, row = 64 B = 4 x 16B chunks,
// chunk swizzle: c' = c ^ (row & 3).
#define TILE_B 8192
#define STAGE_B (2 * TILE_B)      // A, W
#define GEMM_SMEM (3 * STAGE_B)   // 48 KB, 3 stages

// MODE: 0 = relu + fp16 out, 1 = f32 + bias out, 2 = fused final out
template <int MODE, bool DUAL>
__global__ void __launch_bounds__(256, 2)
gemm_mma_kernel(const __half* __restrict__ A,
                const __half* __restrict__ W1,    // (N, Kd) K-major fp16
                const __half* __restrict__ W2,    // DUAL: second weight set
                const float* __restrict__ bias1,
                const float* __restrict__ bias2,
                float* __restrict__ Cf32,
                __half* __restrict__ Ch1,
                __half* __restrict__ Ch2,
                const float* __restrict__ glp,    // MODE 2
                const float* __restrict__ pointp, // MODE 2
                int Kd, int Ncols, int nhalf)
{
    extern __shared__ char smem[];
    const uint32_t sbase = smem_u32_of(smem);
    const int tid = threadIdx.x;
    const int wid = tid >> 5;
    const int lane = tid & 31;
    const int wm = wid & 1;       // 2 M-blocks of 64
    const int wn = wid >> 1;      // 4 N-blocks of 32

    int bxn = blockIdx.x;
    const __half* Wsel = W1;
    const float* bias = bias1;
    __half* Ch = Ch1;
    if (DUAL && bxn >= nhalf) {
        bxn -= nhalf;
        Wsel = W2; bias = bias2; Ch = Ch2;
    }

    const __half* At = A + (size_t)blockIdx.y * 128 * Kd;
    const __half* Wt = Wsel + (size_t)bxn * 128 * Kd;

    float acc[4][4][4];
#pragma unroll
    for (int i = 0; i < 4; i++)
#pragma unroll
        for (int j = 0; j < 4; j++)
#pragma unroll
            for (int r = 0; r < 4; r++) acc[i][j][r] = 0.0f;

    const int nch = Kd >> 5;

    // fill one chunk's 2 tiles into a stage
    auto fill = [&](int ck) {
        const int k0 = ck << 5;
        const uint32_t st = sbase + (ck % 3) * STAGE_B;
#pragma unroll
        for (int it = 0; it < 2; it++) {
            int idx = tid + it * 256;          // 0..511
            int row = idx >> 2, cc = idx & 3;
            uint32_t soff = row * 64 + ((cc ^ (row & 3)) << 4);
            size_t goff = (size_t)row * Kd + k0 + cc * 8;
            CP_ASYNC16(st + 0 * TILE_B + soff, At + goff);
            CP_ASYNC16(st + 1 * TILE_B + soff, Wt + goff);
        }
    };

    fill(0); CP_COMMIT();
    fill(1); CP_COMMIT();

    const int a_row_in = lane & 15;
    const int a_kb     = lane >> 4;
    const int b_n_in   = ((lane >> 4) << 3) + (lane & 7);
    const int b_kb     = (lane >> 3) & 1;

    for (int c = 0; c < nch; c++) {
        if (c + 2 < nch) fill(c + 2);
        CP_COMMIT();
        CP_WAIT2();
        __syncthreads();

        const uint32_t stg = sbase + (c % 3) * STAGE_B;
        const uint32_t sA = stg;
        const uint32_t sW = stg + TILE_B;

#pragma unroll
        for (int s = 0; s < 2; s++) {
            uint32_t bf[2][4];
#pragma unroll
            for (int np = 0; np < 2; np++) {
                int n = wn * 32 + np * 16 + b_n_in;
                int cc = s * 2 + b_kb;
                uint32_t bd = sW + n * 64 + ((cc ^ (n & 3)) << 4);
                LDSM_X4(bf[np][0], bf[np][1], bf[np][2], bf[np][3], bd);
            }
#pragma unroll
            for (int mt = 0; mt < 4; mt++) {
                int row = wm * 64 + mt * 16 + a_row_in;
                int cc = s * 2 + a_kb;
                uint32_t af[4];
                uint32_t ad = sA + row * 64 + ((cc ^ (row & 3)) << 4);
                LDSM_X4(af[0], af[1], af[2], af[3], ad);
#pragma unroll
                for (int nt = 0; nt < 4; nt++) {
                    uint32_t b0 = bf[nt >> 1][(nt & 1) * 2];
                    uint32_t b1 = bf[nt >> 1][(nt & 1) * 2 + 1];
                    MMA_F16(acc[mt][nt], af, b0, b1);
                }
            }
        }
        __syncthreads();
    }

    // epilogue
    const int rbase = blockIdx.y * 128 + wm * 64 + (lane >> 2);
    const int cbase = bxn * 128 + wn * 32 + ((lane & 3) << 1);
#pragma unroll
    for (int mt = 0; mt < 4; mt++) {
#pragma unroll
        for (int half = 0; half < 2; half++) {
            const int row = rbase + mt * 16 + half * 8;
#pragma unroll
            for (int nt = 0; nt < 4; nt++) {
                const int col = cbase + nt * 8;
                float v0 = acc[mt][nt][half * 2 + 0] + bias[col];
                float v1 = acc[mt][nt][half * 2 + 1] + bias[col + 1];
                if (MODE == 0) {
                    v0 = fmaxf(v0, 0.0f);
                    v1 = fmaxf(v1, 0.0f);
                    __half2 h = __floats2half2_rn(v0, v1);
                    *(__half2*)(Ch + (size_t)row * Ncols + col) = h;
                } else if (MODE == 1) {
                    float2 v; v.x = v0; v.y = v1;
                    *(float2*)(Cf32 + (size_t)row * Ncols + col) = v;
                } else {
                    // out = point + sigmoid(gl) * delta
                    size_t o = (size_t)row * Ncols + col;
                    float g0 = glp[o], g1 = glp[o + 1];
                    float s0 = 1.0f / (1.0f + expf(-g0));
                    float s1 = 1.0f / (1.0f + expf(-g1));
                    float2 v;
                    v.x = pointp[o]     + s0 * v0;
                    v.y = pointp[o + 1] + s1 * v1;
                    *(float2*)(Cf32 + o) = v;
                }
            }
        }
    }
}

// ---------------- KNN (top-3) + weighted gather + fp16 concat -----------
__global__ __launch_bounds__(256)
void knn_gather_kernel(const float* __restrict__ patch_center,  // (B,Np,3)
                       const float* __restrict__ coord,         // (B,Ni,3)
                       const float* __restrict__ point_token)   // (B,Np,512)
{
    __shared__ float sx[NI], sy[NI], sz[NI], sm[NI];
    const int b = blockIdx.y;

    for (int i = threadIdx.x; i < NI; i += blockDim.x) {
        const float* cc = coord + ((size_t)b * NI + i) * 3;
        sx[i] = cc[0]; sy[i] = cc[1]; sz[i] = cc[2];
        sm[i] = g_maskF[b * NI + i];
    }
    __syncthreads();

    const int warp = threadIdx.x >> 5;
    const int lane = threadIdx.x & 31;
    const int p = blockIdx.x * 8 + warp;

    const float* q = patch_center + ((size_t)b * NP + p) * 3;
    const float qx = q[0], qy = q[1], qz = q[2];
    const float qs = qx * qx + qy * qy + qz * qz;

    const float INF = __int_as_float(0x7f800000);
    float bd0 = INF, bd1 = INF, bd2 = INF;
    int   bi0 = -1,  bi1 = -1,  bi2 = -1;

#pragma unroll 4
    for (int it = 0; it < NI / 32; it++) {
        int c = it * 32 + lane;
        float x = sx[c], y = sy[c], z = sz[c];
        float ss = x * x + y * y + z * z;
        float dot = qx * x + qy * y + qz * z;
        float d = fmaxf(qs + ss - 2.0f * dot, 0.0f);
        if (sm[c] == 0.0f) d = INF;
        if (d < bd2) {
            if (d < bd1) {
                bd2 = bd1; bi2 = bi1;
                if (d < bd0) { bd1 = bd0; bi1 = bi0; bd0 = d; bi0 = c; }
                else         { bd1 = d;   bi1 = c; }
            } else { bd2 = d; bi2 = c; }
        }
    }

    float selD[KNN_K]; int selI[KNN_K];
    int ptr = 0;
#pragma unroll
    for (int r = 0; r < KNN_K; r++) {
        float cand = (ptr == 0) ? bd0 : (ptr == 1) ? bd1 : (ptr == 2) ? bd2 : INF;
        int   ci   = (ptr == 0) ? bi0 : (ptr == 1) ? bi1 : (ptr == 2) ? bi2 : -1;
        float m = cand;
#pragma unroll
        for (int o = 16; o > 0; o >>= 1) m = fminf(m, __shfl_xor_sync(0xffffffffu, m, o));
        unsigned ball = __ballot_sync(0xffffffffu, cand == m);
        int owner = __ffs(ball) - 1;
        selD[r] = m;
        selI[r] = __shfl_sync(0xffffffffu, ci, owner);
        if (lane == owner) ptr++;
        ptr = min(ptr, 3);
    }

    float w[KNN_K], wsum = 0.0f;
#pragma unroll
    for (int r = 0; r < KNN_K; r++) {
        int idx = selI[r];
        float dist = sqrtf(selD[r]);
        float valid = (idx >= 0) ? sm[idx] : 0.0f;
        w[r] = valid / fmaxf(dist, EPS_);
        wsum += w[r];
    }
    float inv = 1.0f / fmaxf(wsum, EPS_);
#pragma unroll
    for (int r = 0; r < KNN_K; r++) {
        w[r] *= inv;
        if (selI[r] < 0) selI[r] = 0;
    }

    const size_t row = (size_t)b * NP + p;
    const float* f0 = g_ifeat + ((size_t)b * NI + selI[0]) * DO;
    const float* f1 = g_ifeat + ((size_t)b * NI + selI[1]) * DO;
    const float* f2 = g_ifeat + ((size_t)b * NI + selI[2]) * DO;
    const float* pt = point_token + row * DP;
    __half* xr = g_X + row * XDIM;

#pragma unroll 4
    for (int c = lane * 2; c < DO; c += 64) {
        // point half (pairs for vectorized half2 store)
        float2 pv = *(const float2*)(pt + c);
        *(__half2*)(xr + c) = __floats2half2_rn(pv.x, pv.y);
        // aligned half
        float a0 = w[0] * f0[c]     + w[1] * f1[c]     + w[2] * f2[c];
        float a1 = w[0] * f0[c + 1] + w[1] * f1[c + 1] + w[2] * f2[c + 1];
        *(__half2*)(xr + DP + c) = __floats2half2_rn(a0, a1);
    }
}

// ---------------- launch --------------------------------------------------
extern "C" void kernel_launch(void* const* d_in, const int* in_sizes, int n_in,
                              void* d_out, int out_size)
{
    const float* point_token  = (const float*)d_in[0];
    const float* patch_center = (const float*)d_in[1];
    const float* image_token  = (const float*)d_in[2];
    const float* image_coord  = (const float*)d_in[3];
    const void*  mask_raw     =               d_in[4];
    const float* img_w1  = (const float*)d_in[5];
    const float* img_b1  = (const float*)d_in[6];
    const float* img_w2  = (const float*)d_in[7];
    const float* img_b2  = (const float*)d_in[8];
    const float* gate_w1 = (const float*)d_in[9];
    const float* gate_b1 = (const float*)d_in[10];
    const float* gate_w2 = (const float*)d_in[11];
    const float* gate_b2 = (const float*)d_in[12];
    const float* delta_w1 = (const float*)d_in[13];
    const float* delta_b1 = (const float*)d_in[14];
    const float* delta_w2 = (const float*)d_in[15];
    const float* delta_b2 = (const float*)d_in[16];
    float* out = (float*)d_out;

    __half *X, *Gh, *Dh, *I, *Hi;
    __half *iw1, *iw2, *gw1, *gw2, *dw1, *dw2;
    float *ifeat, *gl;
    cudaGetSymbolAddress((void**)&X,  g_X);
    cudaGetSymbolAddress((void**)&Gh, g_Gh);
    cudaGetSymbolAddress((void**)&Dh, g_Dh);
    cudaGetSymbolAddress((void**)&I,  g_I);
    cudaGetSymbolAddress((void**)&Hi, g_Hi);
    cudaGetSymbolAddress((void**)&iw1, g_iw1);
    cudaGetSymbolAddress((void**)&iw2, g_iw2);
    cudaGetSymbolAddress((void**)&gw1, g_gw1);
    cudaGetSymbolAddress((void**)&gw2, g_gw2);
    cudaGetSymbolAddress((void**)&dw1, g_dw1);
    cudaGetSymbolAddress((void**)&dw2, g_dw2);
    cudaGetSymbolAddress((void**)&ifeat, g_ifeat);
    cudaGetSymbolAddress((void**)&gl, g_gl);

    cudaFuncSetAttribute(gemm_mma_kernel<0, false>, cudaFuncAttributeMaxDynamicSharedMemorySize, GEMM_SMEM);
    cudaFuncSetAttribute(gemm_mma_kernel<0, true>,  cudaFuncAttributeMaxDynamicSharedMemorySize, GEMM_SMEM);
    cudaFuncSetAttribute(gemm_mma_kernel<1, false>, cudaFuncAttributeMaxDynamicSharedMemorySize, GEMM_SMEM);
    cudaFuncSetAttribute(gemm_mma_kernel<2, false>, cudaFuncAttributeMaxDynamicSharedMemorySize, GEMM_SMEM);

    // 1. mask
    probe_mask_kernel<<<1, 1>>>(mask_raw);
    normalize_mask_kernel<<<(NIMG + 255) / 256, 256>>>(mask_raw);

    // 2. weight transpose to fp16 (W (K,N) -> (N,K))
    tsplit_kernel<<<dim3(HH / 32, DI / 32),   dim3(32, 32)>>>(img_w1,  iw1, DI,   HH);
    tsplit_kernel<<<dim3(DO / 32, HH / 32),   dim3(32, 32)>>>(img_w2,  iw2, HH,   DO);
    tsplit_kernel<<<dim3(HH / 32, XDIM / 32), dim3(32, 32)>>>(gate_w1, gw1, XDIM, HH);
    tsplit_kernel<<<dim3(DO / 32, HH / 32),   dim3(32, 32)>>>(gate_w2, gw2, HH,   DO);
    tsplit_kernel<<<dim3(HH / 32, XDIM / 32), dim3(32, 32)>>>(delta_w1, dw1, XDIM, HH);
    tsplit_kernel<<<dim3(DO / 32, HH / 32),   dim3(32, 32)>>>(delta_w2, dw2, HH,   DO);

    // 3. image token convert + image MLP
    cvt_kernel<<<((size_t)NIMG * DI / 2 + 255) / 256, 256>>>(image_token, I, (size_t)NIMG * DI / 2);
    gemm_mma_kernel<0, false><<<dim3(HH / 128, NIMG / 128), 256, GEMM_SMEM>>>(
        I, iw1, nullptr, img_b1, nullptr,
        nullptr, Hi, nullptr, nullptr, nullptr, DI, HH, 0);
    gemm_mma_kernel<1, false><<<dim3(DO / 128, NIMG / 128), 256, GEMM_SMEM>>>(
        Hi, iw2, nullptr, img_b2, nullptr,
        ifeat, nullptr, nullptr, nullptr, nullptr, HH, DO, 0);

    // 4. KNN + gather -> fp16 concat X
    knn_gather_kernel<<<dim3(NP / 8, B_), 256>>>(patch_center, image_coord, point_token);

    // 5. fused gate+delta layer-1 (shared X)
    gemm_mma_kernel<0, true><<<dim3(2 * HH / 128, NQ / 128), 256, GEMM_SMEM>>>(
        X, gw1, dw1, gate_b1, delta_b1,
        nullptr, Gh, Dh, nullptr, nullptr, XDIM, HH, HH / 128);

    // 6. gate layer-2 -> gl (f32 logits)
    gemm_mma_kernel<1, false><<<dim3(DO / 128, NQ / 128), 256, GEMM_SMEM>>>(
        Gh, gw2, nullptr, gate_b2, nullptr,
        gl, nullptr, nullptr, nullptr, nullptr, HH, DO, 0);

    // 7. delta layer-2 fused with final gate/residual -> out
    gemm_mma_kernel<2, false><<<dim3(DO / 128, NQ / 128), 256, GEMM_SMEM>>>(
        Dh, dw2, nullptr, delta_b2, nullptr,
        out, nullptr, nullptr, gl, point_token, HH, DO, 0);
}

// round 6
// speedup vs baseline: 6.2621x; 1.2640x over previous
#include <cuda_runtime.h>
#include <cuda_fp16.h>
#include <math.h>
#include <stdint.h>

// ---------------- problem constants (shape-specialized) ----------------
#define B_   4
#define NP   8192
#define NI   1024
#define DP   512
#define DI   768
#define HH   512
#define DO   512
#define NQ   (B_ * NP)        // 32768 query rows
#define NIMG (B_ * NI)        // 4096 image rows
#define XDIM (DP + DO)        // 1024 concat dim
#define KNN_K 3
#define EPS_ 1e-6f

// ---------------- device scratch (static; no allocations allowed) ------
__device__ __half g_X  [(size_t)NQ * XDIM];     // 64 MB
__device__ __half g_Gh [(size_t)NQ * HH];       // 32 MB
__device__ __half g_Dh [(size_t)NQ * HH];       // 32 MB
__device__ __half g_I  [(size_t)NIMG * DI];     //  6 MB
__device__ __half g_Hi [(size_t)NIMG * HH];     //  4 MB
__device__ __half g_ifeat[(size_t)NIMG * DO];   //  4 MB (fp16 now)
// transposed weights, layout (N, K) K-major, fp16
__device__ __half g_iw1[(size_t)HH * DI];
__device__ __half g_iw2[(size_t)DO * HH];
__device__ __half g_gw1[(size_t)HH * XDIM];
__device__ __half g_gw2[(size_t)DO * HH];
__device__ __half g_dw1[(size_t)HH * XDIM];
__device__ __half g_dw2[(size_t)DO * HH];
__device__ float g_maskF[NIMG];

// ---------------- helpers ----------------------------------------------
__device__ __forceinline__ uint32_t smem_u32_of(const void* p) {
    uint32_t a;
    asm("{ .reg .u64 t; cvta.to.shared.u64 t, %1; cvt.u32.u64 %0, t; }" : "=r"(a) : "l"(p));
    return a;
}

#define CP_ASYNC16(dst, src) \
    asm volatile("cp.async.cg.shared.global [%0], [%1], 16;" :: "r"(dst), "l"(src))
#define CP_COMMIT() asm volatile("cp.async.commit_group;" ::: "memory")
#define CP_WAIT2()  asm volatile("cp.async.wait_group 2;" ::: "memory")

#define LDSM_X4(r0, r1, r2, r3, addr) \
    asm volatile("ldmatrix.sync.aligned.m8n8.x4.shared.b16 {%0,%1,%2,%3}, [%4];" \
        : "=r"(r0), "=r"(r1), "=r"(r2), "=r"(r3) : "r"(addr))

#define MMA_F16(d, a, b0v, b1v)                                                \
    asm volatile("mma.sync.aligned.m16n8k16.row.col.f32.f16.f16.f32 "          \
        "{%0,%1,%2,%3}, {%4,%5,%6,%7}, {%8,%9}, {%0,%1,%2,%3};"                \
        : "+f"((d)[0]), "+f"((d)[1]), "+f"((d)[2]), "+f"((d)[3])               \
        : "r"((a)[0]), "r"((a)[1]), "r"((a)[2]), "r"((a)[3]),                  \
          "r"(b0v), "r"(b1v))

// ---------------- merged mask probe+normalize (1 block) -----------------
// mode 0 = float32, 1 = int32, 2 = bytes (bool)
__global__ void mask_kernel(const void* mask) {
    const unsigned int* w = (const unsigned int*)mask;
    bool floatHit = false, multiByte = false;
#pragma unroll
    for (int i = 0; i < 16; i++) {
        unsigned int v = w[i];
        if (v == 0x3F800000u) floatHit = true;
        else if (v & 0xFFFFFF00u) multiByte = true;
    }
    const int mode = floatHit ? 0 : (multiByte ? 2 : 1);
    for (int i = threadIdx.x; i < NIMG; i += blockDim.x) {
        float v;
        if (mode == 0)      v = ((const float*)mask)[i];
        else if (mode == 1) v = (float)((const int*)mask)[i];
        else                v = (float)((const unsigned char*)mask)[i];
        g_maskF[i] = (v != 0.0f) ? 1.0f : 0.0f;
    }
}

// ---------------- batched weight transpose: 6x W(K,N) -> (N,K) fp16 -----
struct TS6 {
    const float* W[6];
    __half* T[6];
    int K[6];
    int N[6];
    int start[7];
};

__global__ void tsplit_all_kernel(TS6 e) {
    __shared__ float t[32][33];
    int bx = blockIdx.x;
    int m = 0;
    while (bx >= e.start[m + 1]) m++;
    const int local = bx - e.start[m];
    const int K = e.K[m], N = e.N[m];
    const int nt = N >> 5;
    const int n0 = (local % nt) << 5;
    const int k0 = (local / nt) << 5;
    const int tx = threadIdx.x, ty = threadIdx.y;
    t[ty][tx] = e.W[m][(size_t)(k0 + ty) * N + n0 + tx];
    __syncthreads();
    e.T[m][(size_t)(n0 + ty) * K + k0 + tx] = __float2half_rn(t[tx][ty]);
}

// ---------------- f32 -> fp16 convert -----------------------------------
__global__ void cvt_kernel(const float* __restrict__ src,
                           __half* __restrict__ dst, size_t n)
{
    size_t i = (size_t)blockIdx.x * blockDim.x + threadIdx.x;
    if (i >= n) return;
    float2 v = ((const float2*)src)[i];
    ((__half2*)dst)[i] = __floats2half2_rn(v.x, v.y);
}

// ---------------- mma.sync fp16 GEMM, K-chunk 64 -------------------------
// C(M,N) = A(M,Kd) @ W^T(N,Kd), fp16 in, f32 accum.
// CTA tile 128x128, K-chunk 64 fp16 (row = 128B = 8 x 16B chunks),
// swizzle: chunk' = chunk ^ (row & 7). 3-stage cp.async pipeline.
#define TILE_B 16384
#define STAGE_B (2 * TILE_B)      // A, W   = 32 KB
#define GEMM_SMEM (3 * STAGE_B)   // 96 KB, 3 stages

// shared K-loop body: runs full K over (At, Wt), accumulating into acc
struct FragCtx {
    uint32_t sbase;
    int tid, wm, wn;
    int a_row_in, a_kb, b_n_in, b_kb;
};

__device__ __forceinline__ void gemm_kloop(const FragCtx& fc,
                                           const __half* __restrict__ At,
                                           const __half* __restrict__ Wt,
                                           int Kd, float acc[4][4][4])
{
    const int nch = Kd >> 6;
    auto fill = [&](int ck) {
        const int k0 = ck << 6;
        const uint32_t st = fc.sbase + (ck % 3) * STAGE_B;
#pragma unroll
        for (int it = 0; it < 4; it++) {
            int i = fc.tid + (it << 8);          // 0..1023
            int row = i >> 3, cc = i & 7;
            uint32_t soff = row * 128 + (((cc ^ row) & 7) << 4);
            size_t goff = (size_t)row * Kd + k0 + cc * 8;
            CP_ASYNC16(st + soff, At + goff);
        }
#pragma unroll
        for (int it = 0; it < 4; it++) {
            int i = fc.tid + (it << 8);
            int row = i >> 3, cc = i & 7;
            uint32_t soff = TILE_B + row * 128 + (((cc ^ row) & 7) << 4);
            size_t goff = (size_t)row * Kd + k0 + cc * 8;
            CP_ASYNC16(st + soff, Wt + goff);
        }
    };

    fill(0); CP_COMMIT();
    fill(1); CP_COMMIT();

    for (int c = 0; c < nch; c++) {
        if (c + 2 < nch) fill(c + 2);
        CP_COMMIT();
        CP_WAIT2();
        __syncthreads();

        const uint32_t stg = fc.sbase + (c % 3) * STAGE_B;
        const uint32_t sA = stg;
        const uint32_t sW = stg + TILE_B;

#pragma unroll
        for (int s = 0; s < 4; s++) {
            uint32_t bf[2][4];
#pragma unroll
            for (int np = 0; np < 2; np++) {
                int n = fc.wn * 32 + np * 16 + fc.b_n_in;
                int cc = (s << 1) + fc.b_kb;
                uint32_t bd = sW + n * 128 + (((cc ^ n) & 7) << 4);
                LDSM_X4(bf[np][0], bf[np][1], bf[np][2], bf[np][3], bd);
            }
#pragma unroll
            for (int mt = 0; mt < 4; mt++) {
                int row = fc.wm * 64 + mt * 16 + fc.a_row_in;
                int cc = (s << 1) + fc.a_kb;
                uint32_t af[4];
                uint32_t ad = sA + row * 128 + (((cc ^ row) & 7) << 4);
                LDSM_X4(af[0], af[1], af[2], af[3], ad);
#pragma unroll
                for (int nt = 0; nt < 4; nt++) {
                    uint32_t b0 = bf[nt >> 1][(nt & 1) * 2];
                    uint32_t b1 = bf[nt >> 1][(nt & 1) * 2 + 1];
                    MMA_F16(acc[mt][nt], af, b0, b1);
                }
            }
        }
        __syncthreads();
    }
}

__device__ __forceinline__ FragCtx make_ctx(const char* smem) {
    FragCtx fc;
    fc.sbase = smem_u32_of(smem);
    fc.tid = threadIdx.x;
    const int wid = fc.tid >> 5;
    const int lane = fc.tid & 31;
    fc.wm = wid & 1;
    fc.wn = wid >> 1;
    fc.a_row_in = lane & 15;
    fc.a_kb = lane >> 4;
    fc.b_n_in = ((lane >> 4) << 3) + (lane & 7);
    fc.b_kb = (lane >> 3) & 1;
    return fc;
}

// MODE 0 = relu + fp16 out, MODE 1 = bias only + fp16 out
template <int MODE, bool DUAL>
__global__ void __launch_bounds__(256, 2)
gemm_mma_kernel(const __half* __restrict__ A,
                const __half* __restrict__ W1,    // (N, Kd) K-major fp16
                const __half* __restrict__ W2,
                const float* __restrict__ bias1,
                const float* __restrict__ bias2,
                __half* __restrict__ Ch1,
                __half* __restrict__ Ch2,
                int Kd, int Ncols, int nhalf)
{
    extern __shared__ char smem[];
    FragCtx fc = make_ctx(smem);
    const int lane = threadIdx.x & 31;

    int bxn = blockIdx.x;
    const __half* Wsel = W1;
    const float* bias = bias1;
    __half* Ch = Ch1;
    if (DUAL && bxn >= nhalf) {
        bxn -= nhalf;
        Wsel = W2; bias = bias2; Ch = Ch2;
    }

    const __half* At = A + (size_t)blockIdx.y * 128 * Kd;
    const __half* Wt = Wsel + (size_t)bxn * 128 * Kd;

    float acc[4][4][4];
#pragma unroll
    for (int i = 0; i < 4; i++)
#pragma unroll
        for (int j = 0; j < 4; j++)
#pragma unroll
            for (int r = 0; r < 4; r++) acc[i][j][r] = 0.0f;

    gemm_kloop(fc, At, Wt, Kd, acc);

    const int rbase = blockIdx.y * 128 + fc.wm * 64 + (lane >> 2);
    const int cbase = bxn * 128 + fc.wn * 32 + ((lane & 3) << 1);
#pragma unroll
    for (int mt = 0; mt < 4; mt++) {
#pragma unroll
        for (int half = 0; half < 2; half++) {
            const int row = rbase + mt * 16 + half * 8;
#pragma unroll
            for (int nt = 0; nt < 4; nt++) {
                const int col = cbase + nt * 8;
                float v0 = acc[mt][nt][half * 2 + 0] + bias[col];
                float v1 = acc[mt][nt][half * 2 + 1] + bias[col + 1];
                if (MODE == 0) { v0 = fmaxf(v0, 0.0f); v1 = fmaxf(v1, 0.0f); }
                *(__half2*)(Ch + (size_t)row * Ncols + col) = __floats2half2_rn(v0, v1);
            }
        }
    }
}

// ---------------- fused gate-L2 + delta-L2 + sigmoid + residual ----------
__global__ void __launch_bounds__(256, 1)
gemm_fused2_kernel(const __half* __restrict__ Gh,
                   const __half* __restrict__ Dh,
                   const __half* __restrict__ Wg,   // (DO, HH) K-major
                   const __half* __restrict__ Wd,
                   const float* __restrict__ bg,
                   const float* __restrict__ bdl,
                   const float* __restrict__ pointp,
                   float* __restrict__ out)
{
    extern __shared__ char smem[];
    FragCtx fc = make_ctx(smem);
    const int lane = threadIdx.x & 31;

    float acc[4][4][4];
#pragma unroll
    for (int i = 0; i < 4; i++)
#pragma unroll
        for (int j = 0; j < 4; j++)
#pragma unroll
            for (int r = 0; r < 4; r++) acc[i][j][r] = 0.0f;

    // phase A: gate logits
    gemm_kloop(fc, Gh + (size_t)blockIdx.y * 128 * HH,
                   Wg + (size_t)blockIdx.x * 128 * HH, HH, acc);

    const int rbase = blockIdx.y * 128 + fc.wm * 64 + (lane >> 2);
    const int cbase = blockIdx.x * 128 + fc.wn * 32 + ((lane & 3) << 1);

    // sigmoid, packed into 32 half2 regs
    uint32_t sig[4][2][4];
#pragma unroll
    for (int mt = 0; mt < 4; mt++)
#pragma unroll
        for (int half = 0; half < 2; half++)
#pragma unroll
            for (int nt = 0; nt < 4; nt++) {
                const int col = cbase + nt * 8;
                float g0 = acc[mt][nt][half * 2 + 0] + bg[col];
                float g1 = acc[mt][nt][half * 2 + 1] + bg[col + 1];
                float s0 = 1.0f / (1.0f + expf(-g0));
                float s1 = 1.0f / (1.0f + expf(-g1));
                __half2 h = __floats2half2_rn(s0, s1);
                sig[mt][half][nt] = *(uint32_t*)&h;
                acc[mt][nt][half * 2 + 0] = 0.0f;
                acc[mt][nt][half * 2 + 1] = 0.0f;
            }

    // phase B: delta logits
    gemm_kloop(fc, Dh + (size_t)blockIdx.y * 128 * HH,
                   Wd + (size_t)blockIdx.x * 128 * HH, HH, acc);

    // epilogue: out = point + sigmoid(gate) * delta
#pragma unroll
    for (int mt = 0; mt < 4; mt++) {
#pragma unroll
        for (int half = 0; half < 2; half++) {
            const int row = rbase + mt * 16 + half * 8;
#pragma unroll
            for (int nt = 0; nt < 4; nt++) {
                const int col = cbase + nt * 8;
                size_t o = (size_t)row * DO + col;
                float v0 = acc[mt][nt][half * 2 + 0] + bdl[col];
                float v1 = acc[mt][nt][half * 2 + 1] + bdl[col + 1];
                __half2 hs = *(__half2*)&sig[mt][half][nt];
                float2 s = __half22float2(hs);
                float2 v;
                v.x = pointp[o]     + s.x * v0;
                v.y = pointp[o + 1] + s.y * v1;
                *(float2*)(out + o) = v;
            }
        }
    }
}

// ---------------- KNN (top-3) + weighted gather + fp16 concat -----------
__global__ __launch_bounds__(256)
void knn_gather_kernel(const float* __restrict__ patch_center,  // (B,Np,3)
                       const float* __restrict__ coord,         // (B,Ni,3)
                       const float* __restrict__ point_token)   // (B,Np,512)
{
    __shared__ float sx[NI], sy[NI], sz[NI], sm[NI];
    const int b = blockIdx.y;

    for (int i = threadIdx.x; i < NI; i += blockDim.x) {
        const float* cc = coord + ((size_t)b * NI + i) * 3;
        sx[i] = cc[0]; sy[i] = cc[1]; sz[i] = cc[2];
        sm[i] = g_maskF[b * NI + i];
    }
    __syncthreads();

    const int warp = threadIdx.x >> 5;
    const int lane = threadIdx.x & 31;
    const int p = blockIdx.x * 8 + warp;

    const float* q = patch_center + ((size_t)b * NP + p) * 3;
    const float qx = q[0], qy = q[1], qz = q[2];
    const float qs = qx * qx + qy * qy + qz * qz;

    const float INF = __int_as_float(0x7f800000);
    float bd0 = INF, bd1 = INF, bd2 = INF;
    int   bi0 = -1,  bi1 = -1,  bi2 = -1;

#pragma unroll 4
    for (int it = 0; it < NI / 32; it++) {
        int c = it * 32 + lane;
        float x = sx[c], y = sy[c], z = sz[c];
        float ss = x * x + y * y + z * z;
        float dot = qx * x + qy * y + qz * z;
        float d = fmaxf(qs + ss - 2.0f * dot, 0.0f);
        if (sm[c] == 0.0f) d = INF;
        if (d < bd2) {
            if (d < bd1) {
                bd2 = bd1; bi2 = bi1;
                if (d < bd0) { bd1 = bd0; bi1 = bi0; bd0 = d; bi0 = c; }
                else         { bd1 = d;   bi1 = c; }
            } else { bd2 = d; bi2 = c; }
        }
    }

    float selD[KNN_K]; int selI[KNN_K];
    int ptr = 0;
#pragma unroll
    for (int r = 0; r < KNN_K; r++) {
        float cand = (ptr == 0) ? bd0 : (ptr == 1) ? bd1 : (ptr == 2) ? bd2 : INF;
        int   ci   = (ptr == 0) ? bi0 : (ptr == 1) ? bi1 : (ptr == 2) ? bi2 : -1;
        float m = cand;
#pragma unroll
        for (int o = 16; o > 0; o >>= 1) m = fminf(m, __shfl_xor_sync(0xffffffffu, m, o));
        unsigned ball = __ballot_sync(0xffffffffu, cand == m);
        int owner = __ffs(ball) - 1;
        selD[r] = m;
        selI[r] = __shfl_sync(0xffffffffu, ci, owner);
        if (lane == owner) ptr++;
        ptr = min(ptr, 3);
    }

    float w[KNN_K], wsum = 0.0f;
#pragma unroll
    for (int r = 0; r < KNN_K; r++) {
        int idx = selI[r];
        float dist = sqrtf(selD[r]);
        float valid = (idx >= 0) ? sm[idx] : 0.0f;
        w[r] = valid / fmaxf(dist, EPS_);
        wsum += w[r];
    }
    float inv = 1.0f / fmaxf(wsum, EPS_);
#pragma unroll
    for (int r = 0; r < KNN_K; r++) {
        w[r] *= inv;
        if (selI[r] < 0) selI[r] = 0;
    }

    const size_t row = (size_t)b * NP + p;
    const __half* f0 = g_ifeat + ((size_t)b * NI + selI[0]) * DO;
    const __half* f1 = g_ifeat + ((size_t)b * NI + selI[1]) * DO;
    const __half* f2 = g_ifeat + ((size_t)b * NI + selI[2]) * DO;
    const float* pt = point_token + row * DP;
    __half* xr = g_X + row * XDIM;

#pragma unroll 4
    for (int c = lane * 2; c < DO; c += 64) {
        // point half
        float2 pv = *(const float2*)(pt + c);
        *(__half2*)(xr + c) = __floats2half2_rn(pv.x, pv.y);
        // aligned half (fp16 neighbor features, fp32 combine)
        float2 a0 = __half22float2(*(const __half2*)(f0 + c));
        float2 a1 = __half22float2(*(const __half2*)(f1 + c));
        float2 a2 = __half22float2(*(const __half2*)(f2 + c));
        float r0 = w[0] * a0.x + w[1] * a1.x + w[2] * a2.x;
        float r1 = w[0] * a0.y + w[1] * a1.y + w[2] * a2.y;
        *(__half2*)(xr + DP + c) = __floats2half2_rn(r0, r1);
    }
}

// ---------------- launch --------------------------------------------------
extern "C" void kernel_launch(void* const* d_in, const int* in_sizes, int n_in,
                              void* d_out, int out_size)
{
    const float* point_token  = (const float*)d_in[0];
    const float* patch_center = (const float*)d_in[1];
    const float* image_token  = (const float*)d_in[2];
    const float* image_coord  = (const float*)d_in[3];
    const void*  mask_raw     =               d_in[4];
    const float* img_w1  = (const float*)d_in[5];
    const float* img_b1  = (const float*)d_in[6];
    const float* img_w2  = (const float*)d_in[7];
    const float* img_b2  = (const float*)d_in[8];
    const float* gate_w1 = (const float*)d_in[9];
    const float* gate_b1 = (const float*)d_in[10];
    const float* gate_w2 = (const float*)d_in[11];
    const float* gate_b2 = (const float*)d_in[12];
    const float* delta_w1 = (const float*)d_in[13];
    const float* delta_b1 = (const float*)d_in[14];
    const float* delta_w2 = (const float*)d_in[15];
    const float* delta_b2 = (const float*)d_in[16];
    float* out = (float*)d_out;

    __half *X, *Gh, *Dh, *I, *Hi, *ifeat;
    __half *iw1, *iw2, *gw1, *gw2, *dw1, *dw2;
    cudaGetSymbolAddress((void**)&X,  g_X);
    cudaGetSymbolAddress((void**)&Gh, g_Gh);
    cudaGetSymbolAddress((void**)&Dh, g_Dh);
    cudaGetSymbolAddress((void**)&I,  g_I);
    cudaGetSymbolAddress((void**)&Hi, g_Hi);
    cudaGetSymbolAddress((void**)&ifeat, g_ifeat);
    cudaGetSymbolAddress((void**)&iw1, g_iw1);
    cudaGetSymbolAddress((void**)&iw2, g_iw2);
    cudaGetSymbolAddress((void**)&gw1, g_gw1);
    cudaGetSymbolAddress((void**)&gw2, g_gw2);
    cudaGetSymbolAddress((void**)&dw1, g_dw1);
    cudaGetSymbolAddress((void**)&dw2, g_dw2);

    cudaFuncSetAttribute(gemm_mma_kernel<0, false>, cudaFuncAttributeMaxDynamicSharedMemorySize, GEMM_SMEM);
    cudaFuncSetAttribute(gemm_mma_kernel<0, true>,  cudaFuncAttributeMaxDynamicSharedMemorySize, GEMM_SMEM);
    cudaFuncSetAttribute(gemm_mma_kernel<1, false>, cudaFuncAttributeMaxDynamicSharedMemorySize, GEMM_SMEM);
    cudaFuncSetAttribute(gemm_fused2_kernel,        cudaFuncAttributeMaxDynamicSharedMemorySize, GEMM_SMEM);

    // 1. mask (probe + normalize, one block)
    mask_kernel<<<1, 1024>>>(mask_raw);

    // 2. batched weight transpose to fp16 (W (K,N) -> (N,K))
    TS6 ts;
    ts.W[0] = img_w1;   ts.T[0] = iw1; ts.K[0] = DI;   ts.N[0] = HH;
    ts.W[1] = img_w2;   ts.T[1] = iw2; ts.K[1] = HH;   ts.N[1] = DO;
    ts.W[2] = gate_w1;  ts.T[2] = gw1; ts.K[2] = XDIM; ts.N[2] = HH;
    ts.W[3] = gate_w2;  ts.T[3] = gw2; ts.K[3] = HH;   ts.N[3] = DO;
    ts.W[4] = delta_w1; ts.T[4] = dw1; ts.K[4] = XDIM; ts.N[4] = HH;
    ts.W[5] = delta_w2; ts.T[5] = dw2; ts.K[5] = HH;   ts.N[5] = DO;
    ts.start[0] = 0;
    for (int i = 0; i < 6; i++)
        ts.start[i + 1] = ts.start[i] + (ts.N[i] / 32) * (ts.K[i] / 32);
    tsplit_all_kernel<<<ts.start[6], dim3(32, 32)>>>(ts);

    // 3. image token convert + image MLP (ifeat now fp16)
    cvt_kernel<<<((size_t)NIMG * DI / 2 + 255) / 256, 256>>>(image_token, I, (size_t)NIMG * DI / 2);
    gemm_mma_kernel<0, false><<<dim3(HH / 128, NIMG / 128), 256, GEMM_SMEM>>>(
        I, iw1, nullptr, img_b1, nullptr, Hi, nullptr, DI, HH, 0);
    gemm_mma_kernel<1, false><<<dim3(DO / 128, NIMG / 128), 256, GEMM_SMEM>>>(
        Hi, iw2, nullptr, img_b2, nullptr, ifeat, nullptr, HH, DO, 0);

    // 4. KNN + gather -> fp16 concat X
    knn_gather_kernel<<<dim3(NP / 8, B_), 256>>>(patch_center, image_coord, point_token);

    // 5. fused gate+delta layer-1 (shared X)
    gemm_mma_kernel<0, true><<<dim3(2 * HH / 128, NQ / 128), 256, GEMM_SMEM>>>(
        X, gw1, dw1, gate_b1, delta_b1, Gh, Dh, XDIM, HH, HH / 128);

    // 6. fused gate-L2 + delta-L2 + sigmoid + residual -> out
    gemm_fused2_kernel<<<dim3(DO / 128, NQ / 128), 256, GEMM_SMEM>>>(
        Gh, Dh, gw2, dw2, gate_b2, delta_b2, point_token, out);
}

// round 7
// speedup vs baseline: 6.2884x; 1.0042x over previous
#include <cuda_runtime.h>
#include <cuda_fp16.h>
#include <math.h>
#include <stdint.h>

// ---------------- problem constants (shape-specialized) ----------------
#define B_   4
#define NP   8192
#define NI   1024
#define DP   512
#define DI   768
#define HH   512
#define DO   512
#define NQ   (B_ * NP)        // 32768 query rows
#define NIMG (B_ * NI)        // 4096 image rows
#define XDIM (DP + DO)        // 1024 concat dim
#define KNN_K 3
#define EPS_ 1e-6f

// ---------------- device scratch (static; no allocations allowed) ------
__device__ __half g_X  [(size_t)NQ * XDIM];     // 64 MB
__device__ __half g_Gh [(size_t)NQ * HH];       // 32 MB
__device__ __half g_Dh [(size_t)NQ * HH];       // 32 MB
__device__ __half g_I  [(size_t)NIMG * DI];     //  6 MB
__device__ __half g_Hi [(size_t)NIMG * HH];     //  4 MB
__device__ __half g_ifeat[(size_t)NIMG * DO];   //  4 MB
// transposed weights, layout (N, K) K-major, fp16
__device__ __half g_iw1[(size_t)HH * DI];
__device__ __half g_iw2[(size_t)DO * HH];
__device__ __half g_gw1[(size_t)HH * XDIM];
__device__ __half g_gw2[(size_t)DO * HH];
__device__ __half g_dw1[(size_t)HH * XDIM];
__device__ __half g_dw2[(size_t)DO * HH];

// ---------------- helpers ----------------------------------------------
__device__ __forceinline__ uint32_t smem_u32_of(const void* p) {
    uint32_t a;
    asm("{ .reg .u64 t; cvta.to.shared.u64 t, %1; cvt.u32.u64 %0, t; }" : "=r"(a) : "l"(p));
    return a;
}

#define CP_ASYNC16(dst, src) \
    asm volatile("cp.async.cg.shared.global [%0], [%1], 16;" :: "r"(dst), "l"(src))
#define CP_COMMIT() asm volatile("cp.async.commit_group;" ::: "memory")
#define CP_WAIT2()  asm volatile("cp.async.wait_group 2;" ::: "memory")

#define LDSM_X4(r0, r1, r2, r3, addr) \
    asm volatile("ldmatrix.sync.aligned.m8n8.x4.shared.b16 {%0,%1,%2,%3}, [%4];" \
        : "=r"(r0), "=r"(r1), "=r"(r2), "=r"(r3) : "r"(addr))

#define MMA_F16(d, a, b0v, b1v)                                                \
    asm volatile("mma.sync.aligned.m16n8k16.row.col.f32.f16.f16.f32 "          \
        "{%0,%1,%2,%3}, {%4,%5,%6,%7}, {%8,%9}, {%0,%1,%2,%3};"                \
        : "+f"((d)[0]), "+f"((d)[1]), "+f"((d)[2]), "+f"((d)[3])               \
        : "r"((a)[0]), "r"((a)[1]), "r"((a)[2]), "r"((a)[3]),                  \
          "r"(b0v), "r"(b1v))

// ---------------- batched weight transpose: 6x W(K,N) -> (N,K) fp16 -----
struct TS6 {
    const float* W[6];
    __half* T[6];
    int K[6];
    int N[6];
    int start[7];
};

__global__ void tsplit_all_kernel(TS6 e) {
    __shared__ float t[32][33];
    int bx = blockIdx.x;
    int m = 0;
    while (bx >= e.start[m + 1]) m++;
    const int local = bx - e.start[m];
    const int K = e.K[m], N = e.N[m];
    const int nt = N >> 5;
    const int n0 = (local % nt) << 5;
    const int k0 = (local / nt) << 5;
    const int tx = threadIdx.x, ty = threadIdx.y;
    t[ty][tx] = e.W[m][(size_t)(k0 + ty) * N + n0 + tx];
    __syncthreads();
    e.T[m][(size_t)(n0 + ty) * K + k0 + tx] = __float2half_rn(t[tx][ty]);
}

// ---------------- f32 -> fp16 convert -----------------------------------
__global__ void cvt_kernel(const float* __restrict__ src,
                           __half* __restrict__ dst, size_t n)
{
    size_t i = (size_t)blockIdx.x * blockDim.x + threadIdx.x;
    if (i >= n) return;
    float2 v = ((const float2*)src)[i];
    ((__half2*)dst)[i] = __floats2half2_rn(v.x, v.y);
}

// ---------------- mma.sync fp16 GEMM, K-chunk 64, templated M tile ------
// C(M,N) = A(M,Kd) @ W^T(N,Kd), fp16 in, f32 accum.
// CTA tile (32*MT) x 128, K-chunk 64 fp16 (row = 128B = 8 x 16B chunks),
// swizzle: chunk' = chunk ^ (row & 7). 3-stage cp.async pipeline.
// Warp layout 2 (M) x 4 (N): each warp (16*MT) x 32.
#define W_TILE_B 16384
template <int MT> struct GemmDims {
    static constexpr int A_TILE_B = MT * 32 * 128;     // rows * 128B
    static constexpr int STAGE_B  = A_TILE_B + W_TILE_B;
    static constexpr int SMEM     = 3 * STAGE_B;
    static constexpr int CTA_M    = 32 * MT;
};

struct FragCtx {
    uint32_t sbase;
    int tid, wm, wn;
    int a_row_in, a_kb, b_n_in, b_kb;
};

__device__ __forceinline__ FragCtx make_ctx(const char* smem) {
    FragCtx fc;
    fc.sbase = smem_u32_of(smem);
    fc.tid = threadIdx.x;
    const int wid = fc.tid >> 5;
    const int lane = fc.tid & 31;
    fc.wm = wid & 1;
    fc.wn = wid >> 1;
    fc.a_row_in = lane & 15;
    fc.a_kb = lane >> 4;
    fc.b_n_in = ((lane >> 4) << 3) + (lane & 7);
    fc.b_kb = (lane >> 3) & 1;
    return fc;
}

template <int MT>
__device__ __forceinline__ void gemm_kloop(const FragCtx& fc,
                                           const __half* __restrict__ At,
                                           const __half* __restrict__ Wt,
                                           int Kd, float acc[MT][4][4])
{
    constexpr int ATB = GemmDims<MT>::A_TILE_B;
    constexpr int STB = GemmDims<MT>::STAGE_B;
    const int nch = Kd >> 6;
    auto fill = [&](int ck) {
        const int k0 = ck << 6;
        const uint32_t st = fc.sbase + (ck % 3) * STB;
#pragma unroll
        for (int it = 0; it < MT; it++) {             // A: 32*MT rows
            int i = fc.tid + (it << 8);
            int row = i >> 3, cc = i & 7;
            uint32_t soff = row * 128 + (((cc ^ row) & 7) << 4);
            size_t goff = (size_t)row * Kd + k0 + cc * 8;
            CP_ASYNC16(st + soff, At + goff);
        }
#pragma unroll
        for (int it = 0; it < 4; it++) {              // W: 128 rows
            int i = fc.tid + (it << 8);
            int row = i >> 3, cc = i & 7;
            uint32_t soff = ATB + row * 128 + (((cc ^ row) & 7) << 4);
            size_t goff = (size_t)row * Kd + k0 + cc * 8;
            CP_ASYNC16(st + soff, Wt + goff);
        }
    };

    fill(0); CP_COMMIT();
    fill(1); CP_COMMIT();

    for (int c = 0; c < nch; c++) {
        if (c + 2 < nch) fill(c + 2);
        CP_COMMIT();
        CP_WAIT2();
        __syncthreads();

        const uint32_t stg = fc.sbase + (c % 3) * STB;
        const uint32_t sA = stg;
        const uint32_t sW = stg + ATB;

#pragma unroll
        for (int s = 0; s < 4; s++) {
            uint32_t bf[2][4];
#pragma unroll
            for (int np = 0; np < 2; np++) {
                int n = fc.wn * 32 + np * 16 + fc.b_n_in;
                int cc = (s << 1) + fc.b_kb;
                uint32_t bd = sW + n * 128 + (((cc ^ n) & 7) << 4);
                LDSM_X4(bf[np][0], bf[np][1], bf[np][2], bf[np][3], bd);
            }
#pragma unroll
            for (int mt = 0; mt < MT; mt++) {
                int row = fc.wm * (16 * MT) + mt * 16 + fc.a_row_in;
                int cc = (s << 1) + fc.a_kb;
                uint32_t af[4];
                uint32_t ad = sA + row * 128 + (((cc ^ row) & 7) << 4);
                LDSM_X4(af[0], af[1], af[2], af[3], ad);
#pragma unroll
                for (int nt = 0; nt < 4; nt++) {
                    uint32_t b0 = bf[nt >> 1][(nt & 1) * 2];
                    uint32_t b1 = bf[nt >> 1][(nt & 1) * 2 + 1];
                    MMA_F16(acc[mt][nt], af, b0, b1);
                }
            }
        }
        __syncthreads();
    }
}

// MODE 0 = relu + fp16 out, MODE 1 = bias only + fp16 out
template <int MT, int MODE, bool DUAL>
__global__ void __launch_bounds__(256, 2)
gemm_mma_kernel(const __half* __restrict__ A,
                const __half* __restrict__ W1,    // (N, Kd) K-major fp16
                const __half* __restrict__ W2,
                const float* __restrict__ bias1,
                const float* __restrict__ bias2,
                __half* __restrict__ Ch1,
                __half* __restrict__ Ch2,
                int Kd, int Ncols, int nhalf)
{
    extern __shared__ char smem[];
    FragCtx fc = make_ctx(smem);
    const int lane = threadIdx.x & 31;

    int bxn = blockIdx.x;
    const __half* Wsel = W1;
    const float* bias = bias1;
    __half* Ch = Ch1;
    if (DUAL && bxn >= nhalf) {
        bxn -= nhalf;
        Wsel = W2; bias = bias2; Ch = Ch2;
    }

    const __half* At = A + (size_t)blockIdx.y * GemmDims<MT>::CTA_M * Kd;
    const __half* Wt = Wsel + (size_t)bxn * 128 * Kd;

    float acc[MT][4][4];
#pragma unroll
    for (int i = 0; i < MT; i++)
#pragma unroll
        for (int j = 0; j < 4; j++)
#pragma unroll
            for (int r = 0; r < 4; r++) acc[i][j][r] = 0.0f;

    gemm_kloop<MT>(fc, At, Wt, Kd, acc);

    const int rbase = blockIdx.y * GemmDims<MT>::CTA_M + fc.wm * (16 * MT) + (lane >> 2);
    const int cbase = bxn * 128 + fc.wn * 32 + ((lane & 3) << 1);
#pragma unroll
    for (int mt = 0; mt < MT; mt++) {
#pragma unroll
        for (int half = 0; half < 2; half++) {
            const int row = rbase + mt * 16 + half * 8;
#pragma unroll
            for (int nt = 0; nt < 4; nt++) {
                const int col = cbase + nt * 8;
                float v0 = acc[mt][nt][half * 2 + 0] + bias[col];
                float v1 = acc[mt][nt][half * 2 + 1] + bias[col + 1];
                if (MODE == 0) { v0 = fmaxf(v0, 0.0f); v1 = fmaxf(v1, 0.0f); }
                *(__half2*)(Ch + (size_t)row * Ncols + col) = __floats2half2_rn(v0, v1);
            }
        }
    }
}

// ---------------- fused gate-L2 + delta-L2 + sigmoid + residual ----------
__global__ void __launch_bounds__(256, 1)
gemm_fused2_kernel(const __half* __restrict__ Gh,
                   const __half* __restrict__ Dh,
                   const __half* __restrict__ Wg,   // (DO, HH) K-major
                   const __half* __restrict__ Wd,
                   const float* __restrict__ bg,
                   const float* __restrict__ bdl,
                   const float* __restrict__ pointp,
                   float* __restrict__ out)
{
    extern __shared__ char smem[];
    FragCtx fc = make_ctx(smem);
    const int lane = threadIdx.x & 31;

    float acc[4][4][4];
#pragma unroll
    for (int i = 0; i < 4; i++)
#pragma unroll
        for (int j = 0; j < 4; j++)
#pragma unroll
            for (int r = 0; r < 4; r++) acc[i][j][r] = 0.0f;

    // phase A: gate logits
    gemm_kloop<4>(fc, Gh + (size_t)blockIdx.y * 128 * HH,
                      Wg + (size_t)blockIdx.x * 128 * HH, HH, acc);

    const int rbase = blockIdx.y * 128 + fc.wm * 64 + (lane >> 2);
    const int cbase = blockIdx.x * 128 + fc.wn * 32 + ((lane & 3) << 1);

    // sigmoid, packed into 32 half2 regs
    uint32_t sig[4][2][4];
#pragma unroll
    for (int mt = 0; mt < 4; mt++)
#pragma unroll
        for (int half = 0; half < 2; half++)
#pragma unroll
            for (int nt = 0; nt < 4; nt++) {
                const int col = cbase + nt * 8;
                float g0 = acc[mt][nt][half * 2 + 0] + bg[col];
                float g1 = acc[mt][nt][half * 2 + 1] + bg[col + 1];
                float s0 = 1.0f / (1.0f + expf(-g0));
                float s1 = 1.0f / (1.0f + expf(-g1));
                __half2 h = __floats2half2_rn(s0, s1);
                sig[mt][half][nt] = *(uint32_t*)&h;
                acc[mt][nt][half * 2 + 0] = 0.0f;
                acc[mt][nt][half * 2 + 1] = 0.0f;
            }

    // phase B: delta logits
    gemm_kloop<4>(fc, Dh + (size_t)blockIdx.y * 128 * HH,
                      Wd + (size_t)blockIdx.x * 128 * HH, HH, acc);

    // epilogue: out = point + sigmoid(gate) * delta
#pragma unroll
    for (int mt = 0; mt < 4; mt++) {
#pragma unroll
        for (int half = 0; half < 2; half++) {
            const int row = rbase + mt * 16 + half * 8;
#pragma unroll
            for (int nt = 0; nt < 4; nt++) {
                const int col = cbase + nt * 8;
                size_t o = (size_t)row * DO + col;
                float v0 = acc[mt][nt][half * 2 + 0] + bdl[col];
                float v1 = acc[mt][nt][half * 2 + 1] + bdl[col + 1];
                __half2 hs = *(__half2*)&sig[mt][half][nt];
                float2 s = __half22float2(hs);
                float2 v;
                v.x = pointp[o]     + s.x * v0;
                v.y = pointp[o + 1] + s.y * v1;
                *(float2*)(out + o) = v;
            }
        }
    }
}

// ---------------- KNN (top-3) + gather + fp16 concat, inline mask -------
__global__ __launch_bounds__(256)
void knn_gather_kernel(const float* __restrict__ patch_center,  // (B,Np,3)
                       const float* __restrict__ coord,         // (B,Ni,3)
                       const float* __restrict__ point_token,   // (B,Np,512)
                       const void* __restrict__ mask_raw)       // (B,Ni) dtype probed
{
    __shared__ float sx[NI], sy[NI], sz[NI], sm[NI];
    const int b = blockIdx.y;

    // inline mask dtype probe (uniform across threads; reads 64 bytes)
    const unsigned int* mw = (const unsigned int*)mask_raw;
    bool floatHit = false, multiByte = false;
#pragma unroll
    for (int i = 0; i < 16; i++) {
        unsigned int v = mw[i];
        if (v == 0x3F800000u) floatHit = true;
        else if (v & 0xFFFFFF00u) multiByte = true;
    }
    const int mode = floatHit ? 0 : (multiByte ? 2 : 1);

    for (int i = threadIdx.x; i < NI; i += blockDim.x) {
        const float* cc = coord + ((size_t)b * NI + i) * 3;
        sx[i] = cc[0]; sy[i] = cc[1]; sz[i] = cc[2];
        const int gi = b * NI + i;
        float mv;
        if (mode == 0)      mv = ((const float*)mask_raw)[gi];
        else if (mode == 1) mv = (float)((const int*)mask_raw)[gi];
        else                mv = (float)((const unsigned char*)mask_raw)[gi];
        sm[i] = (mv != 0.0f) ? 1.0f : 0.0f;
    }
    __syncthreads();

    const int warp = threadIdx.x >> 5;
    const int lane = threadIdx.x & 31;
    const int p = blockIdx.x * 8 + warp;

    const float* q = patch_center + ((size_t)b * NP + p) * 3;
    const float qx = q[0], qy = q[1], qz = q[2];
    const float qs = qx * qx + qy * qy + qz * qz;

    const float INF = __int_as_float(0x7f800000);
    float bd0 = INF, bd1 = INF, bd2 = INF;
    int   bi0 = -1,  bi1 = -1,  bi2 = -1;

#pragma unroll 4
    for (int it = 0; it < NI / 32; it++) {
        int c = it * 32 + lane;
        float x = sx[c], y = sy[c], z = sz[c];
        float ss = x * x + y * y + z * z;
        float dot = qx * x + qy * y + qz * z;
        float d = fmaxf(qs + ss - 2.0f * dot, 0.0f);
        if (sm[c] == 0.0f) d = INF;
        if (d < bd2) {
            if (d < bd1) {
                bd2 = bd1; bi2 = bi1;
                if (d < bd0) { bd1 = bd0; bi1 = bi0; bd0 = d; bi0 = c; }
                else         { bd1 = d;   bi1 = c; }
            } else { bd2 = d; bi2 = c; }
        }
    }

    float selD[KNN_K]; int selI[KNN_K];
    int ptr = 0;
#pragma unroll
    for (int r = 0; r < KNN_K; r++) {
        float cand = (ptr == 0) ? bd0 : (ptr == 1) ? bd1 : (ptr == 2) ? bd2 : INF;
        int   ci   = (ptr == 0) ? bi0 : (ptr == 1) ? bi1 : (ptr == 2) ? bi2 : -1;
        float m = cand;
#pragma unroll
        for (int o = 16; o > 0; o >>= 1) m = fminf(m, __shfl_xor_sync(0xffffffffu, m, o));
        unsigned ball = __ballot_sync(0xffffffffu, cand == m);
        int owner = __ffs(ball) - 1;
        selD[r] = m;
        selI[r] = __shfl_sync(0xffffffffu, ci, owner);
        if (lane == owner) ptr++;
        ptr = min(ptr, 3);
    }

    float w[KNN_K], wsum = 0.0f;
#pragma unroll
    for (int r = 0; r < KNN_K; r++) {
        int idx = selI[r];
        float dist = sqrtf(selD[r]);
        float valid = (idx >= 0) ? sm[idx] : 0.0f;
        w[r] = valid / fmaxf(dist, EPS_);
        wsum += w[r];
    }
    float inv = 1.0f / fmaxf(wsum, EPS_);
#pragma unroll
    for (int r = 0; r < KNN_K; r++) {
        w[r] *= inv;
        if (selI[r] < 0) selI[r] = 0;
    }

    const size_t row = (size_t)b * NP + p;
    const __half* f0 = g_ifeat + ((size_t)b * NI + selI[0]) * DO;
    const __half* f1 = g_ifeat + ((size_t)b * NI + selI[1]) * DO;
    const __half* f2 = g_ifeat + ((size_t)b * NI + selI[2]) * DO;
    const float* pt = point_token + row * DP;
    __half* xr = g_X + row * XDIM;

#pragma unroll 4
    for (int c = lane * 2; c < DO; c += 64) {
        float2 pv = *(const float2*)(pt + c);
        *(__half2*)(xr + c) = __floats2half2_rn(pv.x, pv.y);
        float2 a0 = __half22float2(*(const __half2*)(f0 + c));
        float2 a1 = __half22float2(*(const __half2*)(f1 + c));
        float2 a2 = __half22float2(*(const __half2*)(f2 + c));
        float r0 = w[0] * a0.x + w[1] * a1.x + w[2] * a2.x;
        float r1 = w[0] * a0.y + w[1] * a1.y + w[2] * a2.y;
        *(__half2*)(xr + DP + c) = __floats2half2_rn(r0, r1);
    }
}

// ---------------- launch --------------------------------------------------
extern "C" void kernel_launch(void* const* d_in, const int* in_sizes, int n_in,
                              void* d_out, int out_size)
{
    const float* point_token  = (const float*)d_in[0];
    const float* patch_center = (const float*)d_in[1];
    const float* image_token  = (const float*)d_in[2];
    const float* image_coord  = (const float*)d_in[3];
    const void*  mask_raw     =               d_in[4];
    const float* img_w1  = (const float*)d_in[5];
    const float* img_b1  = (const float*)d_in[6];
    const float* img_w2  = (const float*)d_in[7];
    const float* img_b2  = (const float*)d_in[8];
    const float* gate_w1 = (const float*)d_in[9];
    const float* gate_b1 = (const float*)d_in[10];
    const float* gate_w2 = (const float*)d_in[11];
    const float* gate_b2 = (const float*)d_in[12];
    const float* delta_w1 = (const float*)d_in[13];
    const float* delta_b1 = (const float*)d_in[14];
    const float* delta_w2 = (const float*)d_in[15];
    const float* delta_b2 = (const float*)d_in[16];
    float* out = (float*)d_out;

    __half *X, *Gh, *Dh, *I, *Hi, *ifeat;
    __half *iw1, *iw2, *gw1, *gw2, *dw1, *dw2;
    cudaGetSymbolAddress((void**)&X,  g_X);
    cudaGetSymbolAddress((void**)&Gh, g_Gh);
    cudaGetSymbolAddress((void**)&Dh, g_Dh);
    cudaGetSymbolAddress((void**)&I,  g_I);
    cudaGetSymbolAddress((void**)&Hi, g_Hi);
    cudaGetSymbolAddress((void**)&ifeat, g_ifeat);
    cudaGetSymbolAddress((void**)&iw1, g_iw1);
    cudaGetSymbolAddress((void**)&iw2, g_iw2);
    cudaGetSymbolAddress((void**)&gw1, g_gw1);
    cudaGetSymbolAddress((void**)&gw2, g_gw2);
    cudaGetSymbolAddress((void**)&dw1, g_dw1);
    cudaGetSymbolAddress((void**)&dw2, g_dw2);

    constexpr int SM4 = GemmDims<4>::SMEM;   // 96 KB
    constexpr int SM2 = GemmDims<2>::SMEM;   // 72 KB
    cudaFuncSetAttribute(gemm_mma_kernel<2, 0, false>, cudaFuncAttributeMaxDynamicSharedMemorySize, SM2);
    cudaFuncSetAttribute(gemm_mma_kernel<2, 1, false>, cudaFuncAttributeMaxDynamicSharedMemorySize, SM2);
    cudaFuncSetAttribute(gemm_mma_kernel<4, 0, true>,  cudaFuncAttributeMaxDynamicSharedMemorySize, SM4);
    cudaFuncSetAttribute(gemm_fused2_kernel,           cudaFuncAttributeMaxDynamicSharedMemorySize, SM4);

    // 1. batched weight transpose to fp16 (W (K,N) -> (N,K))
    TS6 ts;
    ts.W[0] = img_w1;   ts.T[0] = iw1; ts.K[0] = DI;   ts.N[0] = HH;
    ts.W[1] = img_w2;   ts.T[1] = iw2; ts.K[1] = HH;   ts.N[1] = DO;
    ts.W[2] = gate_w1;  ts.T[2] = gw1; ts.K[2] = XDIM; ts.N[2] = HH;
    ts.W[3] = gate_w2;  ts.T[3] = gw2; ts.K[3] = HH;   ts.N[3] = DO;
    ts.W[4] = delta_w1; ts.T[4] = dw1; ts.K[4] = XDIM; ts.N[4] = HH;
    ts.W[5] = delta_w2; ts.T[5] = dw2; ts.K[5] = HH;   ts.N[5] = DO;
    ts.start[0] = 0;
    for (int i = 0; i < 6; i++)
        ts.start[i + 1] = ts.start[i] + (ts.N[i] / 32) * (ts.K[i] / 32);
    tsplit_all_kernel<<<ts.start[6], dim3(32, 32)>>>(ts);

    // 2. image token convert + image MLP (M=64 tiles -> 256 CTAs each)
    cvt_kernel<<<((size_t)NIMG * DI / 2 + 255) / 256, 256>>>(image_token, I, (size_t)NIMG * DI / 2);
    gemm_mma_kernel<2, 0, false><<<dim3(HH / 128, NIMG / 64), 256, SM2>>>(
        I, iw1, nullptr, img_b1, nullptr, Hi, nullptr, DI, HH, 0);
    gemm_mma_kernel<2, 1, false><<<dim3(DO / 128, NIMG / 64), 256, SM2>>>(
        Hi, iw2, nullptr, img_b2, nullptr, ifeat, nullptr, HH, DO, 0);

    // 3. KNN + gather -> fp16 concat X (mask decoded inline)
    knn_gather_kernel<<<dim3(NP / 8, B_), 256>>>(patch_center, image_coord, point_token, mask_raw);

    // 4. fused gate+delta layer-1 (shared X)
    gemm_mma_kernel<4, 0, true><<<dim3(2 * HH / 128, NQ / 128), 256, SM4>>>(
        X, gw1, dw1, gate_b1, delta_b1, Gh, Dh, XDIM, HH, HH / 128);

    // 5. fused gate-L2 + delta-L2 + sigmoid + residual -> out
    gemm_fused2_kernel<<<dim3(DO / 128, NQ / 128), 256, SM4>>>(
        Gh, Dh, gw2, dw2, gate_b2, delta_b2, point_token, out);
}